// round 2
// baseline (speedup 1.0000x reference)
#include <cuda_runtime.h>
#include <cstdint>

#define LVAL 4096
#define NB 64
#define ROWS_CTA 64
#define KC 64
#define STRIDE 68   // 64 + 4 pad, conflict-free LDS
#define RADIUS 0.9f

// Blaschke basis matrix B[n][l], fp32, built once per launch (L2-resident, 1 MB)
__device__ float g_B[NB * LVAL];

__global__ void build_B_kernel() {
    int idx = blockIdx.x * blockDim.x + threadIdx.x;
    if (idx >= NB * LVAL) return;
    int n = idx >> 12;      // / 4096
    int l = idx & 4095;
    const double TWO_PI = 6.283185307179586476925286766559;
    float theta = (float)((double)n * (TWO_PI / 64.0));
    float t     = (float)((double)l * (TWO_PI / 4095.0));   // linspace(0,2pi,4096) endpoint
    float c = cosf(t - theta);
    const float r = RADIUS;
    float scale = sqrtf(1.0f - r * r);
    g_B[idx] = scale * (1.0f - r * c) / (1.0f - 2.0f * r * c + r * r);
}

__device__ __forceinline__ uint32_t f2tf(float f) {
    uint32_t r; asm("cvt.rna.tf32.f32 %0, %1;" : "=r"(r) : "f"(f)); return r;
}
__device__ __forceinline__ float f2tff(float f) { return __uint_as_float(f2tf(f)); }

// D = A(16x8,row) * B(8x8,col) + D, tf32 inputs (pre-rounded), fp32 accum
__device__ __forceinline__ void mma8(float* c, const uint32_t* a, const uint32_t* b) {
    asm volatile(
        "mma.sync.aligned.m16n8k8.row.col.f32.tf32.tf32.f32 "
        "{%0,%1,%2,%3}, {%4,%5,%6,%7}, {%8,%9}, {%0,%1,%2,%3};\n"
        : "+f"(c[0]), "+f"(c[1]), "+f"(c[2]), "+f"(c[3])
        : "r"(a[0]), "r"(a[1]), "r"(a[2]), "r"(a[3]),
          "r"(b[0]), "r"(b[1]));
}

__global__ __launch_bounds__(128) void afd_fused_kernel(
    const float* __restrict__ x, float* __restrict__ out)
{
    __shared__ float sbuf[2 * NB * STRIDE];   // 8704 floats = 34816 B (static)
    float* s0 = sbuf;                // phase A: x chunk [64][68]; later proj/W [row][n]
    float* s1 = sbuf + NB * STRIDE;  // B chunk [64][68]

    const int tid  = threadIdx.x;
    const int warp = tid >> 5;
    const int lane = tid & 31;
    const int g    = lane >> 2;      // groupID
    const int tig  = lane & 3;       // thread in group
    const int row0 = blockIdx.x * ROWS_CTA;
    const int mo = (warp & 1) * 32;  // phase A: basis offset | phase C: row offset
    const int no = (warp >> 1) * 32; // phase A: row offset   | phase C: l offset

    float acc[8][4];
    #pragma unroll
    for (int i = 0; i < 8; i++)
        #pragma unroll
        for (int j = 0; j < 4; j++) acc[i][j] = 0.f;

    // ================= Phase A: proj[basis, row] = sum_l B[basis,l] * x[row,l] ======
    for (int k0 = 0; k0 < LVAL; k0 += KC) {
        #pragma unroll
        for (int i = 0; i < 8; i++) {
            int idx = tid + i * 128;
            int r = idx >> 4, q = idx & 15;
            float4 v = *(const float4*)(x + (size_t)(row0 + r) * LVAL + k0 + q * 4);
            *(float4*)(s0 + r * STRIDE + q * 4) =
                make_float4(f2tff(v.x), f2tff(v.y), f2tff(v.z), f2tff(v.w));
            float4 u = *(const float4*)(g_B + (size_t)r * LVAL + k0 + q * 4);
            *(float4*)(s1 + r * STRIDE + q * 4) =
                make_float4(f2tff(u.x), f2tff(u.y), f2tff(u.z), f2tff(u.w));
        }
        __syncthreads();

        #pragma unroll
        for (int kk = 0; kk < KC; kk += 8) {
            uint32_t a[2][4], b[4][2];
            #pragma unroll
            for (int mt = 0; mt < 2; mt++) {
                const float* ap = s1 + (mo + mt * 16 + g) * STRIDE + kk + tig;
                a[mt][0] = __float_as_uint(ap[0]);
                a[mt][1] = __float_as_uint(ap[8 * STRIDE]);
                a[mt][2] = __float_as_uint(ap[4]);
                a[mt][3] = __float_as_uint(ap[8 * STRIDE + 4]);
            }
            #pragma unroll
            for (int nt = 0; nt < 4; nt++) {
                const float* bp = s0 + (no + nt * 8 + g) * STRIDE + kk + tig;
                b[nt][0] = __float_as_uint(bp[0]);
                b[nt][1] = __float_as_uint(bp[4]);
            }
            #pragma unroll
            for (int mt = 0; mt < 2; mt++)
                #pragma unroll
                for (int nt = 0; nt < 4; nt++)
                    mma8(acc[mt * 4 + nt], a[mt], b[nt]);
        }
        __syncthreads();
    }

    // ================= Phase B: dump proj to smem [row][basis], softmax(|.|) =======
    #pragma unroll
    for (int mt = 0; mt < 2; mt++)
        #pragma unroll
        for (int nt = 0; nt < 4; nt++) {
            int basis = mo + mt * 16 + g;
            int rr    = no + nt * 8 + 2 * tig;
            s0[(rr    ) * STRIDE + basis    ] = acc[mt * 4 + nt][0];
            s0[(rr + 1) * STRIDE + basis    ] = acc[mt * 4 + nt][1];
            s0[(rr    ) * STRIDE + basis + 8] = acc[mt * 4 + nt][2];
            s0[(rr + 1) * STRIDE + basis + 8] = acc[mt * 4 + nt][3];
        }
    __syncthreads();

    for (int r = warp * 16; r < warp * 16 + 16; r++) {
        float v0 = fabsf(s0[r * STRIDE + lane]);
        float v1 = fabsf(s0[r * STRIDE + lane + 32]);
        float m = fmaxf(v0, v1);
        #pragma unroll
        for (int o = 16; o > 0; o >>= 1) m = fmaxf(m, __shfl_xor_sync(0xffffffffu, m, o));
        float e0 = __expf(v0 - m), e1 = __expf(v1 - m);
        float s = e0 + e1;
        #pragma unroll
        for (int o = 16; o > 0; o >>= 1) s += __shfl_xor_sync(0xffffffffu, s, o);
        float inv = 1.0f / s;
        s0[r * STRIDE + lane     ] = f2tff(e0 * inv);   // W pre-rounded to tf32
        s0[r * STRIDE + lane + 32] = f2tff(e1 * inv);
    }
    __syncthreads();

    // ================= Phase C: out[row,l] = x[row,l] + sum_n W[row,n]*B[n,l] ======
    for (int l0 = 0; l0 < LVAL; l0 += KC) {
        #pragma unroll
        for (int i = 0; i < 8; i++) {
            int idx = tid + i * 128;
            int n = idx >> 4, q = idx & 15;
            float4 u = *(const float4*)(g_B + (size_t)n * LVAL + l0 + q * 4);
            *(float4*)(s1 + n * STRIDE + q * 4) =
                make_float4(f2tff(u.x), f2tff(u.y), f2tff(u.z), f2tff(u.w));
        }
        __syncthreads();

        #pragma unroll
        for (int i = 0; i < 8; i++)
            #pragma unroll
            for (int j = 0; j < 4; j++) acc[i][j] = 0.f;

        #pragma unroll
        for (int kk = 0; kk < NB; kk += 8) {
            uint32_t a[2][4], b[4][2];
            #pragma unroll
            for (int mt = 0; mt < 2; mt++) {
                const float* ap = s0 + (mo + mt * 16 + g) * STRIDE + kk + tig;  // W[row][n]
                a[mt][0] = __float_as_uint(ap[0]);
                a[mt][1] = __float_as_uint(ap[8 * STRIDE]);
                a[mt][2] = __float_as_uint(ap[4]);
                a[mt][3] = __float_as_uint(ap[8 * STRIDE + 4]);
            }
            #pragma unroll
            for (int nt = 0; nt < 4; nt++) {
                const float* bp = s1 + (kk + tig) * STRIDE + no + nt * 8 + g;   // B[n][l]
                b[nt][0] = __float_as_uint(bp[0]);
                b[nt][1] = __float_as_uint(bp[4 * STRIDE]);
            }
            #pragma unroll
            for (int mt = 0; mt < 2; mt++)
                #pragma unroll
                for (int nt = 0; nt < 4; nt++)
                    mma8(acc[mt * 4 + nt], a[mt], b[nt]);
        }

        // epilogue: out = x + attn (x read fresh fp32, exact passthrough)
        #pragma unroll
        for (int mt = 0; mt < 2; mt++)
            #pragma unroll
            for (int nt = 0; nt < 4; nt++) {
                int row = row0 + mo + mt * 16 + g;
                int lc  = l0 + no + nt * 8 + 2 * tig;
                size_t i0 = (size_t)row * LVAL + lc;
                float2 xv = *(const float2*)(x + i0);
                *(float2*)(out + i0) =
                    make_float2(xv.x + acc[mt * 4 + nt][0], xv.y + acc[mt * 4 + nt][1]);
                size_t i1 = i0 + (size_t)8 * LVAL;
                float2 xw = *(const float2*)(x + i1);
                *(float2*)(out + i1) =
                    make_float2(xw.x + acc[mt * 4 + nt][2], xw.y + acc[mt * 4 + nt][3]);
            }
        __syncthreads();
    }
}

extern "C" void kernel_launch(void* const* d_in, const int* in_sizes, int n_in,
                              void* d_out, int out_size) {
    const float* x = (const float*)d_in[0];
    float* out = (float*)d_out;
    (void)in_sizes; (void)n_in; (void)out_size;

    build_B_kernel<<<(NB * LVAL + 255) / 256, 256>>>();
    afd_fused_kernel<<<16384 / ROWS_CTA, 128>>>(x, out);
}

// round 3
// speedup vs baseline: 1.0204x; 1.0204x over previous
#include <cuda_runtime.h>
#include <cstdint>

#define LVAL 4096
#define NB 64
#define ROWS_CTA 64
#define KC 64
#define STRIDE 68   // 64 + 4 pad, conflict-free LDS
#define RADIUS 0.9f

// Blaschke basis matrix B[n][l], fp32, built once per launch (L2-resident, 1 MB)
__device__ float g_B[NB * LVAL];

__global__ void build_B_kernel() {
    int idx = blockIdx.x * blockDim.x + threadIdx.x;
    if (idx >= NB * LVAL) return;
    int n = idx >> 12;      // / 4096
    int l = idx & 4095;
    const double TWO_PI = 6.283185307179586476925286766559;
    float theta = (float)((double)n * (TWO_PI / 64.0));
    float t     = (float)((double)l * (TWO_PI / 4095.0));   // linspace(0,2pi,4096) endpoint
    float c = cosf(t - theta);
    const float r = RADIUS;
    float scale = sqrtf(1.0f - r * r);
    g_B[idx] = scale * (1.0f - r * c) / (1.0f - 2.0f * r * c + r * r);
}

__device__ __forceinline__ uint32_t f2tf(float f) {
    uint32_t r; asm("cvt.rna.tf32.f32 %0, %1;" : "=r"(r) : "f"(f)); return r;
}
__device__ __forceinline__ float f2tff(float f) { return __uint_as_float(f2tf(f)); }

// D = A(16x8,row) * B(8x8,col) + D, tf32 inputs (pre-rounded), fp32 accum
__device__ __forceinline__ void mma8(float* c, const uint32_t* a, const uint32_t* b) {
    asm volatile(
        "mma.sync.aligned.m16n8k8.row.col.f32.tf32.tf32.f32 "
        "{%0,%1,%2,%3}, {%4,%5,%6,%7}, {%8,%9}, {%0,%1,%2,%3};\n"
        : "+f"(c[0]), "+f"(c[1]), "+f"(c[2]), "+f"(c[3])
        : "r"(a[0]), "r"(a[1]), "r"(a[2]), "r"(a[3]),
          "r"(b[0]), "r"(b[1]));
}

__global__ __launch_bounds__(128) void afd_fused_kernel(
    const float* __restrict__ x, float* __restrict__ out)
{
    __shared__ float sbuf[2 * NB * STRIDE];   // 8704 floats = 34816 B (static)
    float* s0 = sbuf;                // phase A: x chunk [64][68]; later proj/W [row][n]
    float* s1 = sbuf + NB * STRIDE;  // B chunk [64][68]

    const int tid  = threadIdx.x;
    const int warp = tid >> 5;
    const int lane = tid & 31;
    const int g    = lane >> 2;      // groupID
    const int tig  = lane & 3;       // thread in group
    const int row0 = blockIdx.x * ROWS_CTA;
    const int mo = (warp & 1) * 32;  // phase A: basis offset | phase C: row offset
    const int no = (warp >> 1) * 32; // phase A: row offset   | phase C: l offset

    float acc[8][4];
    #pragma unroll
    for (int i = 0; i < 8; i++)
        #pragma unroll
        for (int j = 0; j < 4; j++) acc[i][j] = 0.f;

    // ================= Phase A: proj[basis, row] = sum_l B[basis,l] * x[row,l] ======
    for (int k0 = 0; k0 < LVAL; k0 += KC) {
        #pragma unroll
        for (int i = 0; i < 8; i++) {
            int idx = tid + i * 128;
            int r = idx >> 4, q = idx & 15;
            float4 v = *(const float4*)(x + (size_t)(row0 + r) * LVAL + k0 + q * 4);
            *(float4*)(s0 + r * STRIDE + q * 4) =
                make_float4(f2tff(v.x), f2tff(v.y), f2tff(v.z), f2tff(v.w));
            float4 u = *(const float4*)(g_B + (size_t)r * LVAL + k0 + q * 4);
            *(float4*)(s1 + r * STRIDE + q * 4) =
                make_float4(f2tff(u.x), f2tff(u.y), f2tff(u.z), f2tff(u.w));
        }
        __syncthreads();

        #pragma unroll
        for (int kk = 0; kk < KC; kk += 8) {
            uint32_t a[2][4], b[4][2];
            #pragma unroll
            for (int mt = 0; mt < 2; mt++) {
                const float* ap = s1 + (mo + mt * 16 + g) * STRIDE + kk + tig;
                a[mt][0] = __float_as_uint(ap[0]);
                a[mt][1] = __float_as_uint(ap[8 * STRIDE]);
                a[mt][2] = __float_as_uint(ap[4]);
                a[mt][3] = __float_as_uint(ap[8 * STRIDE + 4]);
            }
            #pragma unroll
            for (int nt = 0; nt < 4; nt++) {
                const float* bp = s0 + (no + nt * 8 + g) * STRIDE + kk + tig;
                b[nt][0] = __float_as_uint(bp[0]);
                b[nt][1] = __float_as_uint(bp[4]);
            }
            #pragma unroll
            for (int mt = 0; mt < 2; mt++)
                #pragma unroll
                for (int nt = 0; nt < 4; nt++)
                    mma8(acc[mt * 4 + nt], a[mt], b[nt]);
        }
        __syncthreads();
    }

    // ================= Phase B: dump proj to smem [row][basis], softmax(|.|) =======
    #pragma unroll
    for (int mt = 0; mt < 2; mt++)
        #pragma unroll
        for (int nt = 0; nt < 4; nt++) {
            int basis = mo + mt * 16 + g;
            int rr    = no + nt * 8 + 2 * tig;
            s0[(rr    ) * STRIDE + basis    ] = acc[mt * 4 + nt][0];
            s0[(rr + 1) * STRIDE + basis    ] = acc[mt * 4 + nt][1];
            s0[(rr    ) * STRIDE + basis + 8] = acc[mt * 4 + nt][2];
            s0[(rr + 1) * STRIDE + basis + 8] = acc[mt * 4 + nt][3];
        }
    __syncthreads();

    for (int r = warp * 16; r < warp * 16 + 16; r++) {
        float v0 = fabsf(s0[r * STRIDE + lane]);
        float v1 = fabsf(s0[r * STRIDE + lane + 32]);
        float m = fmaxf(v0, v1);
        #pragma unroll
        for (int o = 16; o > 0; o >>= 1) m = fmaxf(m, __shfl_xor_sync(0xffffffffu, m, o));
        float e0 = __expf(v0 - m), e1 = __expf(v1 - m);
        float s = e0 + e1;
        #pragma unroll
        for (int o = 16; o > 0; o >>= 1) s += __shfl_xor_sync(0xffffffffu, s, o);
        float inv = 1.0f / s;
        s0[r * STRIDE + lane     ] = f2tff(e0 * inv);   // W pre-rounded to tf32
        s0[r * STRIDE + lane + 32] = f2tff(e1 * inv);
    }
    __syncthreads();

    // ================= Phase C: out[row,l] = x[row,l] + sum_n W[row,n]*B[n,l] ======
    for (int l0 = 0; l0 < LVAL; l0 += KC) {
        #pragma unroll
        for (int i = 0; i < 8; i++) {
            int idx = tid + i * 128;
            int n = idx >> 4, q = idx & 15;
            float4 u = *(const float4*)(g_B + (size_t)n * LVAL + l0 + q * 4);
            *(float4*)(s1 + n * STRIDE + q * 4) =
                make_float4(f2tff(u.x), f2tff(u.y), f2tff(u.z), f2tff(u.w));
        }
        __syncthreads();

        #pragma unroll
        for (int i = 0; i < 8; i++)
            #pragma unroll
            for (int j = 0; j < 4; j++) acc[i][j] = 0.f;

        #pragma unroll
        for (int kk = 0; kk < NB; kk += 8) {
            uint32_t a[2][4], b[4][2];
            #pragma unroll
            for (int mt = 0; mt < 2; mt++) {
                const float* ap = s0 + (mo + mt * 16 + g) * STRIDE + kk + tig;  // W[row][n]
                a[mt][0] = __float_as_uint(ap[0]);
                a[mt][1] = __float_as_uint(ap[8 * STRIDE]);
                a[mt][2] = __float_as_uint(ap[4]);
                a[mt][3] = __float_as_uint(ap[8 * STRIDE + 4]);
            }
            #pragma unroll
            for (int nt = 0; nt < 4; nt++) {
                const float* bp = s1 + (kk + tig) * STRIDE + no + nt * 8 + g;   // B[n][l]
                b[nt][0] = __float_as_uint(bp[0]);
                b[nt][1] = __float_as_uint(bp[4 * STRIDE]);
            }
            #pragma unroll
            for (int mt = 0; mt < 2; mt++)
                #pragma unroll
                for (int nt = 0; nt < 4; nt++)
                    mma8(acc[mt * 4 + nt], a[mt], b[nt]);
        }

        // epilogue: out = x + attn (x read fresh fp32, exact passthrough)
        #pragma unroll
        for (int mt = 0; mt < 2; mt++)
            #pragma unroll
            for (int nt = 0; nt < 4; nt++) {
                int row = row0 + mo + mt * 16 + g;
                int lc  = l0 + no + nt * 8 + 2 * tig;
                size_t i0 = (size_t)row * LVAL + lc;
                float2 xv = *(const float2*)(x + i0);
                *(float2*)(out + i0) =
                    make_float2(xv.x + acc[mt * 4 + nt][0], xv.y + acc[mt * 4 + nt][1]);
                size_t i1 = i0 + (size_t)8 * LVAL;
                float2 xw = *(const float2*)(x + i1);
                *(float2*)(out + i1) =
                    make_float2(xw.x + acc[mt * 4 + nt][2], xw.y + acc[mt * 4 + nt][3]);
            }
        __syncthreads();
    }
}

extern "C" void kernel_launch(void* const* d_in, const int* in_sizes, int n_in,
                              void* d_out, int out_size) {
    const float* x = (const float*)d_in[0];
    float* out = (float*)d_out;
    (void)in_sizes; (void)n_in; (void)out_size;

    build_B_kernel<<<(NB * LVAL + 255) / 256, 256>>>();
    afd_fused_kernel<<<16384 / ROWS_CTA, 128>>>(x, out);
}

// round 4
// speedup vs baseline: 1.0528x; 1.0318x over previous
#include <cuda_runtime.h>
#include <cstdint>

#define LVAL 4096
#define NB 64
#define ROWS_CTA 64
#define KC 64
#define NCHUNK (LVAL / KC)   // 64
#define SA 68                // stride for row-major, k-inner arrays (bank: 4g+tig, conflict-free)
#define SC 72                // stride for phase-C B chunk (bank: 8*tig+g, conflict-free)
#define THREADS 256
#define RADIUS 0.9f

// Blaschke basis matrix B[n][l], fp32, built once per launch (L2-resident, 1 MB)
__device__ float g_B[NB * LVAL];

__global__ void build_B_kernel() {
    int idx = blockIdx.x * blockDim.x + threadIdx.x;
    if (idx >= NB * LVAL) return;
    int n = idx >> 12;
    int l = idx & 4095;
    const double TWO_PI = 6.283185307179586476925286766559;
    float theta = (float)((double)n * (TWO_PI / 64.0));
    float t     = (float)((double)l * (TWO_PI / 4095.0));   // linspace(0,2pi,4096), endpoint
    float c = cosf(t - theta);
    const float r = RADIUS;
    float scale = sqrtf(1.0f - r * r);
    g_B[idx] = scale * (1.0f - r * c) / (1.0f - 2.0f * r * c + r * r);
}

__device__ __forceinline__ unsigned smem_u32(const void* p) {
    return (unsigned)__cvta_generic_to_shared(p);
}
__device__ __forceinline__ void cp16(unsigned dst, const void* src) {
    asm volatile("cp.async.ca.shared.global [%0], [%1], 16;\n" :: "r"(dst), "l"(src));
}
__device__ __forceinline__ void cp_commit() {
    asm volatile("cp.async.commit_group;\n" ::: "memory");
}
template <int N>
__device__ __forceinline__ void cp_wait() {
    asm volatile("cp.async.wait_group %0;\n" :: "n"(N) : "memory");
}

// exact hi/lo split: hi = v with low 13 mantissa bits cleared (valid tf32), lo = v - hi (exact)
__device__ __forceinline__ float tf_hi(float v) {
    return __uint_as_float(__float_as_uint(v) & 0xFFFFE000u);
}
__device__ __forceinline__ uint32_t rn_tf32(float f) {
    uint32_t r; asm("cvt.rna.tf32.f32 %0, %1;" : "=r"(r) : "f"(f)); return r;
}

// D = A(16x8,row) * B(8x8,col) + D, tf32 inputs, fp32 accum
__device__ __forceinline__ void mma8(float* c, const uint32_t* a, const uint32_t* b) {
    asm volatile(
        "mma.sync.aligned.m16n8k8.row.col.f32.tf32.tf32.f32 "
        "{%0,%1,%2,%3}, {%4,%5,%6,%7}, {%8,%9}, {%0,%1,%2,%3};\n"
        : "+f"(c[0]), "+f"(c[1]), "+f"(c[2]), "+f"(c[3])
        : "r"(a[0]), "r"(a[1]), "r"(a[2]), "r"(a[3]),
          "r"(b[0]), "r"(b[1]));
}

// Dynamic smem layout (floats):
//   [0,     4352)  x chunk stage 0 / proj / Wh
//   [4352,  8704)  x chunk stage 1 / Wl
//   [8704, 13312)  B chunk stage 0 (phase A: 64*SA used; phase C: 64*SC=4608)
//   [13312,17920)  B chunk stage 1
#define SMEM_FLOATS 17920
#define SMEM_BYTES (SMEM_FLOATS * 4)

__global__ __launch_bounds__(THREADS, 2) void afd_kernel(
    const float* __restrict__ x, float* __restrict__ out)
{
    extern __shared__ float sm[];
    const int tid  = threadIdx.x;
    const int warp = tid >> 5;
    const int lane = tid & 31;
    const int g    = lane >> 2;
    const int tig  = lane & 3;
    const int row0 = blockIdx.x * ROWS_CTA;

    float* sX0 = sm;
    float* sX1 = sm + 4352;
    float* sB0 = sm + 8704;
    float* sB1 = sm + 13312;

    // ---------------- Phase A: proj[basis, row] = sum_l B[basis,l]*x[row,l] (3xTF32 split)
    {
        const int bas0 = (warp & 3) * 16;   // 16 basis rows per warp tile
        const int ro0  = (warp >> 2) * 32;  // 32 data rows per warp tile

        float acc[4][4];
        #pragma unroll
        for (int i = 0; i < 4; i++)
            #pragma unroll
            for (int j = 0; j < 4; j++) acc[i][j] = 0.f;

        // prologue: issue chunk 0
        {
            float* dx = sX0; float* db = sB0;
            #pragma unroll
            for (int i = 0; i < 4; i++) {
                int idx = tid + i * 256; int r = idx >> 4, q = idx & 15;
                cp16(smem_u32(dx + r * SA + q * 4), x + (size_t)(row0 + r) * LVAL + q * 4);
                cp16(smem_u32(db + r * SA + q * 4), g_B + (size_t)r * LVAL + q * 4);
            }
            cp_commit();
        }

        for (int c = 0; c < NCHUNK; c++) {
            if (c + 1 < NCHUNK) {
                int k0 = (c + 1) * KC;
                float* dx = ((c + 1) & 1) ? sX1 : sX0;
                float* db = ((c + 1) & 1) ? sB1 : sB0;
                #pragma unroll
                for (int i = 0; i < 4; i++) {
                    int idx = tid + i * 256; int r = idx >> 4, q = idx & 15;
                    cp16(smem_u32(dx + r * SA + q * 4), x + (size_t)(row0 + r) * LVAL + k0 + q * 4);
                    cp16(smem_u32(db + r * SA + q * 4), g_B + (size_t)r * LVAL + k0 + q * 4);
                }
                cp_commit();
                cp_wait<1>();
            } else {
                cp_wait<0>();
            }
            __syncthreads();

            const float* bx = (c & 1) ? sX1 : sX0;
            const float* bb = (c & 1) ? sB1 : sB0;

            #pragma unroll
            for (int kk = 0; kk < KC; kk += 8) {
                const float* ap = bb + (bas0 + g) * SA + kk + tig;
                float ar0 = ap[0], ar1 = ap[8 * SA], ar2 = ap[4], ar3 = ap[8 * SA + 4];
                float h0 = tf_hi(ar0), h1 = tf_hi(ar1), h2 = tf_hi(ar2), h3 = tf_hi(ar3);
                uint32_t ah[4] = { __float_as_uint(h0), __float_as_uint(h1),
                                   __float_as_uint(h2), __float_as_uint(h3) };
                uint32_t al[4] = { __float_as_uint(ar0 - h0), __float_as_uint(ar1 - h1),
                                   __float_as_uint(ar2 - h2), __float_as_uint(ar3 - h3) };
                #pragma unroll
                for (int nt = 0; nt < 4; nt++) {
                    const float* bp = bx + (ro0 + nt * 8 + g) * SA + kk + tig;
                    float b0 = bp[0], b1 = bp[4];
                    float bh0 = tf_hi(b0), bh1 = tf_hi(b1);
                    uint32_t bh[2] = { __float_as_uint(bh0), __float_as_uint(bh1) };
                    uint32_t bl[2] = { __float_as_uint(b0 - bh0), __float_as_uint(b1 - bh1) };
                    mma8(acc[nt], ah, bh);
                    mma8(acc[nt], ah, bl);
                    mma8(acc[nt], al, bh);
                }
            }
            __syncthreads();
        }

        // ---------------- Phase B: dump proj -> smem [row][basis], softmax(|.|), split W
        #pragma unroll
        for (int nt = 0; nt < 4; nt++) {
            int rr = ro0 + nt * 8 + 2 * tig;
            int bs = bas0 + g;
            sm[rr * SA + bs]           = acc[nt][0];
            sm[(rr + 1) * SA + bs]     = acc[nt][1];
            sm[rr * SA + bs + 8]       = acc[nt][2];
            sm[(rr + 1) * SA + bs + 8] = acc[nt][3];
        }
    }
    __syncthreads();

    {
        float* sWh = sX0;  // in-place over proj
        float* sWl = sX1;
        for (int r = warp * 8; r < warp * 8 + 8; r++) {
            float v0 = fabsf(sm[r * SA + lane]);
            float v1 = fabsf(sm[r * SA + lane + 32]);
            float m = fmaxf(v0, v1);
            #pragma unroll
            for (int o = 16; o > 0; o >>= 1) m = fmaxf(m, __shfl_xor_sync(0xffffffffu, m, o));
            float e0 = __expf(v0 - m), e1 = __expf(v1 - m);
            float s = e0 + e1;
            #pragma unroll
            for (int o = 16; o > 0; o >>= 1) s += __shfl_xor_sync(0xffffffffu, s, o);
            float inv = 1.0f / s;
            float w0 = e0 * inv, w1 = e1 * inv;
            float h0 = tf_hi(w0), h1 = tf_hi(w1);
            sWh[r * SA + lane]      = h0;
            sWl[r * SA + lane]      = w0 - h0;
            sWh[r * SA + lane + 32] = h1;
            sWl[r * SA + lane + 32] = w1 - h1;
        }
    }
    __syncthreads();

    // ---------------- Phase C: out[row,l] = x[row,l] + sum_n W[row,n]*B[n,l] (W split)
    {
        const float* sWh = sX0;
        const float* sWl = sX1;
        const int r0  = (warp & 3) * 16;   // 16 output rows per warp tile
        const int lo0 = (warp >> 2) * 32;  // 32 l-columns per warp tile

        // prologue: issue chunk 0
        {
            #pragma unroll
            for (int i = 0; i < 4; i++) {
                int idx = tid + i * 256; int n = idx >> 4, q = idx & 15;
                cp16(smem_u32(sB0 + n * SC + q * 4), g_B + (size_t)n * LVAL + q * 4);
            }
            cp_commit();
        }

        for (int c = 0; c < NCHUNK; c++) {
            if (c + 1 < NCHUNK) {
                int l0n = (c + 1) * KC;
                float* db = ((c + 1) & 1) ? sB1 : sB0;
                #pragma unroll
                for (int i = 0; i < 4; i++) {
                    int idx = tid + i * 256; int n = idx >> 4, q = idx & 15;
                    cp16(smem_u32(db + n * SC + q * 4), g_B + (size_t)n * LVAL + l0n + q * 4);
                }
                cp_commit();
                cp_wait<1>();
            } else {
                cp_wait<0>();
            }
            __syncthreads();

            const float* bc = (c & 1) ? sB1 : sB0;

            float acc[4][4];
            #pragma unroll
            for (int i = 0; i < 4; i++)
                #pragma unroll
                for (int j = 0; j < 4; j++) acc[i][j] = 0.f;

            #pragma unroll
            for (int kk = 0; kk < NB; kk += 8) {
                const float* hp = sWh + (r0 + g) * SA + kk + tig;
                const float* lp = sWl + (r0 + g) * SA + kk + tig;
                uint32_t ah[4] = { __float_as_uint(hp[0]), __float_as_uint(hp[8 * SA]),
                                   __float_as_uint(hp[4]), __float_as_uint(hp[8 * SA + 4]) };
                uint32_t al[4] = { __float_as_uint(lp[0]), __float_as_uint(lp[8 * SA]),
                                   __float_as_uint(lp[4]), __float_as_uint(lp[8 * SA + 4]) };
                #pragma unroll
                for (int nt = 0; nt < 4; nt++) {
                    const float* bp = bc + (kk + tig) * SC + lo0 + nt * 8 + g;
                    uint32_t b[2] = { rn_tf32(bp[0]), rn_tf32(bp[4 * SC]) };
                    mma8(acc[nt], ah, b);
                    mma8(acc[nt], al, b);
                }
            }
            __syncthreads();   // all warps done with bc before next iter's cp.async reuses it

            // epilogue: out = x + attn
            int l0 = c * KC;
            #pragma unroll
            for (int nt = 0; nt < 4; nt++) {
                int row = row0 + r0 + g;
                int lc  = l0 + lo0 + nt * 8 + 2 * tig;
                size_t i0 = (size_t)row * LVAL + lc;
                float2 xv = *(const float2*)(x + i0);
                *(float2*)(out + i0) = make_float2(xv.x + acc[nt][0], xv.y + acc[nt][1]);
                size_t i1 = i0 + (size_t)8 * LVAL;
                float2 xw = *(const float2*)(x + i1);
                *(float2*)(out + i1) = make_float2(xw.x + acc[nt][2], xw.y + acc[nt][3]);
            }
        }
    }
}

extern "C" void kernel_launch(void* const* d_in, const int* in_sizes, int n_in,
                              void* d_out, int out_size) {
    const float* x = (const float*)d_in[0];
    float* out = (float*)d_out;
    (void)in_sizes; (void)n_in; (void)out_size;

    cudaFuncSetAttribute(afd_kernel, cudaFuncAttributeMaxDynamicSharedMemorySize, SMEM_BYTES);
    build_B_kernel<<<(NB * LVAL + 255) / 256, 256>>>();
    afd_kernel<<<16384 / ROWS_CTA, THREADS, SMEM_BYTES>>>(x, out);
}

// round 5
// speedup vs baseline: 1.0615x; 1.0082x over previous
#include <cuda_runtime.h>
#include <cstdint>

#define LVAL 4096
#define NB 64
#define ROWS_CTA 64
#define KC 64
#define NCHUNK (LVAL / KC)   // 64
#define SA 68                // stride for row-major, k-inner arrays (bank: 4g+tig, conflict-free)
#define SC 72                // stride for phase-C B chunk (bank: 8*tig+g, conflict-free)
#define THREADS 256
#define RADIUS 0.9f

// Blaschke basis matrix B[n][l], fp32, built once per launch (L2-resident, 1 MB)
__device__ float g_B[NB * LVAL];

__global__ void build_B_kernel() {
    int idx = blockIdx.x * blockDim.x + threadIdx.x;
    if (idx >= NB * LVAL) return;
    int n = idx >> 12;
    int l = idx & 4095;
    const double TWO_PI = 6.283185307179586476925286766559;
    float theta = (float)((double)n * (TWO_PI / 64.0));
    float t     = (float)((double)l * (TWO_PI / 4095.0));   // linspace(0,2pi,4096), endpoint
    float c = cosf(t - theta);
    const float r = RADIUS;
    float scale = sqrtf(1.0f - r * r);
    g_B[idx] = scale * (1.0f - r * c) / (1.0f - 2.0f * r * c + r * r);
}

__device__ __forceinline__ unsigned smem_u32(const void* p) {
    return (unsigned)__cvta_generic_to_shared(p);
}
__device__ __forceinline__ void cp16(unsigned dst, const void* src) {
    asm volatile("cp.async.ca.shared.global [%0], [%1], 16;\n" :: "r"(dst), "l"(src));
}
__device__ __forceinline__ void cp_commit() {
    asm volatile("cp.async.commit_group;\n" ::: "memory");
}
template <int N>
__device__ __forceinline__ void cp_wait() {
    asm volatile("cp.async.wait_group %0;\n" :: "n"(N) : "memory");
}

// exact hi/lo split: hi = v with low 13 mantissa bits cleared (valid tf32), lo = v - hi (exact)
__device__ __forceinline__ float tf_hi(float v) {
    return __uint_as_float(__float_as_uint(v) & 0xFFFFE000u);
}
__device__ __forceinline__ uint32_t rn_tf32(float f) {
    uint32_t r; asm("cvt.rna.tf32.f32 %0, %1;" : "=r"(r) : "f"(f)); return r;
}

// D = A(16x8,row) * B(8x8,col) + D, tf32 inputs, fp32 accum
__device__ __forceinline__ void mma8(float* c, const uint32_t* a, const uint32_t* b) {
    asm volatile(
        "mma.sync.aligned.m16n8k8.row.col.f32.tf32.tf32.f32 "
        "{%0,%1,%2,%3}, {%4,%5,%6,%7}, {%8,%9}, {%0,%1,%2,%3};\n"
        : "+f"(c[0]), "+f"(c[1]), "+f"(c[2]), "+f"(c[3])
        : "r"(a[0]), "r"(a[1]), "r"(a[2]), "r"(a[3]),
          "r"(b[0]), "r"(b[1]));
}

// Dynamic smem layout (floats):
//   [0,     4352)  x chunk stage 0 / proj / Wh
//   [4352,  8704)  x chunk stage 1 / Wl
//   [8704, 13312)  B chunk stage 0 (phase A: 64*SA used; phase C: 64*SC=4608)
//   [13312,17920)  B chunk stage 1
#define SMEM_FLOATS 17920
#define SMEM_BYTES (SMEM_FLOATS * 4)

__global__ __launch_bounds__(THREADS, 2) void afd_kernel(
    const float* __restrict__ x, float* __restrict__ out)
{
    extern __shared__ float sm[];
    const int tid  = threadIdx.x;
    const int warp = tid >> 5;
    const int lane = tid & 31;
    const int g    = lane >> 2;
    const int tig  = lane & 3;
    const int row0 = blockIdx.x * ROWS_CTA;

    float* sX0 = sm;
    float* sX1 = sm + 4352;
    float* sB0 = sm + 8704;
    float* sB1 = sm + 13312;

    // ---------------- Phase A: proj[basis, row] = sum_l B[basis,l]*x[row,l] (3xTF32 split)
    {
        const int bas0 = (warp & 3) * 16;   // 16 basis rows per warp tile
        const int ro0  = (warp >> 2) * 32;  // 32 data rows per warp tile

        float acc[4][4];
        #pragma unroll
        for (int i = 0; i < 4; i++)
            #pragma unroll
            for (int j = 0; j < 4; j++) acc[i][j] = 0.f;

        // prologue: issue chunk 0
        {
            float* dx = sX0; float* db = sB0;
            #pragma unroll
            for (int i = 0; i < 4; i++) {
                int idx = tid + i * 256; int r = idx >> 4, q = idx & 15;
                cp16(smem_u32(dx + r * SA + q * 4), x + (size_t)(row0 + r) * LVAL + q * 4);
                cp16(smem_u32(db + r * SA + q * 4), g_B + (size_t)r * LVAL + q * 4);
            }
            cp_commit();
        }

        for (int c = 0; c < NCHUNK; c++) {
            if (c + 1 < NCHUNK) {
                int k0 = (c + 1) * KC;
                float* dx = ((c + 1) & 1) ? sX1 : sX0;
                float* db = ((c + 1) & 1) ? sB1 : sB0;
                #pragma unroll
                for (int i = 0; i < 4; i++) {
                    int idx = tid + i * 256; int r = idx >> 4, q = idx & 15;
                    cp16(smem_u32(dx + r * SA + q * 4), x + (size_t)(row0 + r) * LVAL + k0 + q * 4);
                    cp16(smem_u32(db + r * SA + q * 4), g_B + (size_t)r * LVAL + k0 + q * 4);
                }
                cp_commit();
                cp_wait<1>();
            } else {
                cp_wait<0>();
            }
            __syncthreads();

            const float* bx = (c & 1) ? sX1 : sX0;
            const float* bb = (c & 1) ? sB1 : sB0;

            #pragma unroll
            for (int kk = 0; kk < KC; kk += 8) {
                const float* ap = bb + (bas0 + g) * SA + kk + tig;
                float ar0 = ap[0], ar1 = ap[8 * SA], ar2 = ap[4], ar3 = ap[8 * SA + 4];
                float h0 = tf_hi(ar0), h1 = tf_hi(ar1), h2 = tf_hi(ar2), h3 = tf_hi(ar3);
                uint32_t ah[4] = { __float_as_uint(h0), __float_as_uint(h1),
                                   __float_as_uint(h2), __float_as_uint(h3) };
                uint32_t al[4] = { __float_as_uint(ar0 - h0), __float_as_uint(ar1 - h1),
                                   __float_as_uint(ar2 - h2), __float_as_uint(ar3 - h3) };
                #pragma unroll
                for (int nt = 0; nt < 4; nt++) {
                    const float* bp = bx + (ro0 + nt * 8 + g) * SA + kk + tig;
                    float b0 = bp[0], b1 = bp[4];
                    float bh0 = tf_hi(b0), bh1 = tf_hi(b1);
                    uint32_t bh[2] = { __float_as_uint(bh0), __float_as_uint(bh1) };
                    uint32_t bl[2] = { __float_as_uint(b0 - bh0), __float_as_uint(b1 - bh1) };
                    mma8(acc[nt], ah, bh);
                    mma8(acc[nt], ah, bl);
                    mma8(acc[nt], al, bh);
                }
            }
            __syncthreads();
        }

        // ---------------- Phase B: dump proj -> smem [row][basis], softmax(|.|), split W
        #pragma unroll
        for (int nt = 0; nt < 4; nt++) {
            int rr = ro0 + nt * 8 + 2 * tig;
            int bs = bas0 + g;
            sm[rr * SA + bs]           = acc[nt][0];
            sm[(rr + 1) * SA + bs]     = acc[nt][1];
            sm[rr * SA + bs + 8]       = acc[nt][2];
            sm[(rr + 1) * SA + bs + 8] = acc[nt][3];
        }
    }
    __syncthreads();

    {
        float* sWh = sX0;  // in-place over proj
        float* sWl = sX1;
        for (int r = warp * 8; r < warp * 8 + 8; r++) {
            float v0 = fabsf(sm[r * SA + lane]);
            float v1 = fabsf(sm[r * SA + lane + 32]);
            float m = fmaxf(v0, v1);
            #pragma unroll
            for (int o = 16; o > 0; o >>= 1) m = fmaxf(m, __shfl_xor_sync(0xffffffffu, m, o));
            float e0 = __expf(v0 - m), e1 = __expf(v1 - m);
            float s = e0 + e1;
            #pragma unroll
            for (int o = 16; o > 0; o >>= 1) s += __shfl_xor_sync(0xffffffffu, s, o);
            float inv = 1.0f / s;
            float w0 = e0 * inv, w1 = e1 * inv;
            float h0 = tf_hi(w0), h1 = tf_hi(w1);
            sWh[r * SA + lane]      = h0;
            sWl[r * SA + lane]      = w0 - h0;
            sWh[r * SA + lane + 32] = h1;
            sWl[r * SA + lane + 32] = w1 - h1;
        }
    }
    __syncthreads();

    // ---------------- Phase C: out[row,l] = x[row,l] + sum_n W[row,n]*B[n,l] (W split)
    {
        const float* sWh = sX0;
        const float* sWl = sX1;
        const int r0  = (warp & 3) * 16;   // 16 output rows per warp tile
        const int lo0 = (warp >> 2) * 32;  // 32 l-columns per warp tile

        // prologue: issue chunk 0
        {
            #pragma unroll
            for (int i = 0; i < 4; i++) {
                int idx = tid + i * 256; int n = idx >> 4, q = idx & 15;
                cp16(smem_u32(sB0 + n * SC + q * 4), g_B + (size_t)n * LVAL + q * 4);
            }
            cp_commit();
        }

        for (int c = 0; c < NCHUNK; c++) {
            if (c + 1 < NCHUNK) {
                int l0n = (c + 1) * KC;
                float* db = ((c + 1) & 1) ? sB1 : sB0;
                #pragma unroll
                for (int i = 0; i < 4; i++) {
                    int idx = tid + i * 256; int n = idx >> 4, q = idx & 15;
                    cp16(smem_u32(db + n * SC + q * 4), g_B + (size_t)n * LVAL + l0n + q * 4);
                }
                cp_commit();
                cp_wait<1>();
            } else {
                cp_wait<0>();
            }
            __syncthreads();

            const float* bc = (c & 1) ? sB1 : sB0;

            float acc[4][4];
            #pragma unroll
            for (int i = 0; i < 4; i++)
                #pragma unroll
                for (int j = 0; j < 4; j++) acc[i][j] = 0.f;

            #pragma unroll
            for (int kk = 0; kk < NB; kk += 8) {
                const float* hp = sWh + (r0 + g) * SA + kk + tig;
                const float* lp = sWl + (r0 + g) * SA + kk + tig;
                uint32_t ah[4] = { __float_as_uint(hp[0]), __float_as_uint(hp[8 * SA]),
                                   __float_as_uint(hp[4]), __float_as_uint(hp[8 * SA + 4]) };
                uint32_t al[4] = { __float_as_uint(lp[0]), __float_as_uint(lp[8 * SA]),
                                   __float_as_uint(lp[4]), __float_as_uint(lp[8 * SA + 4]) };
                #pragma unroll
                for (int nt = 0; nt < 4; nt++) {
                    const float* bp = bc + (kk + tig) * SC + lo0 + nt * 8 + g;
                    uint32_t b[2] = { rn_tf32(bp[0]), rn_tf32(bp[4 * SC]) };
                    mma8(acc[nt], ah, b);
                    mma8(acc[nt], al, b);
                }
            }
            __syncthreads();   // all warps done with bc before next iter's cp.async reuses it

            // epilogue: out = x + attn
            int l0 = c * KC;
            #pragma unroll
            for (int nt = 0; nt < 4; nt++) {
                int row = row0 + r0 + g;
                int lc  = l0 + lo0 + nt * 8 + 2 * tig;
                size_t i0 = (size_t)row * LVAL + lc;
                float2 xv = *(const float2*)(x + i0);
                *(float2*)(out + i0) = make_float2(xv.x + acc[nt][0], xv.y + acc[nt][1]);
                size_t i1 = i0 + (size_t)8 * LVAL;
                float2 xw = *(const float2*)(x + i1);
                *(float2*)(out + i1) = make_float2(xw.x + acc[nt][2], xw.y + acc[nt][3]);
            }
        }
    }
}

extern "C" void kernel_launch(void* const* d_in, const int* in_sizes, int n_in,
                              void* d_out, int out_size) {
    const float* x = (const float*)d_in[0];
    float* out = (float*)d_out;
    (void)in_sizes; (void)n_in; (void)out_size;

    cudaFuncSetAttribute(afd_kernel, cudaFuncAttributeMaxDynamicSharedMemorySize, SMEM_BYTES);
    build_B_kernel<<<(NB * LVAL + 255) / 256, 256>>>();
    afd_kernel<<<16384 / ROWS_CTA, THREADS, SMEM_BYTES>>>(x, out);
}

// round 6
// speedup vs baseline: 1.0643x; 1.0026x over previous
#include <cuda_runtime.h>
#include <cstdint>

#define LVAL 4096
#define NB 64
#define ROWS_CTA 64
#define KC 64
#define NCHUNK (LVAL / KC)   // 64
#define SA 68                // stride for row-major, k-inner arrays (bank: 4g+tig, conflict-free)
#define SC 72                // stride for phase-C B chunk (bank: 8*tig+g, conflict-free)
#define THREADS 256
#define RADIUS 0.9f

// Blaschke basis matrix B[n][l], fp32, built once per launch (L2-resident, 1 MB)
__device__ float g_B[NB * LVAL];

__global__ void build_B_kernel() {
    int idx = blockIdx.x * blockDim.x + threadIdx.x;
    if (idx >= NB * LVAL) return;
    int n = idx >> 12;
    int l = idx & 4095;
    const double TWO_PI = 6.283185307179586476925286766559;
    float theta = (float)((double)n * (TWO_PI / 64.0));
    float t     = (float)((double)l * (TWO_PI / 4095.0));   // linspace(0,2pi,4096), endpoint
    float c = cosf(t - theta);
    const float r = RADIUS;
    float scale = sqrtf(1.0f - r * r);
    g_B[idx] = scale * (1.0f - r * c) / (1.0f - 2.0f * r * c + r * r);
}

__device__ __forceinline__ unsigned smem_u32(const void* p) {
    return (unsigned)__cvta_generic_to_shared(p);
}
__device__ __forceinline__ void cp16(unsigned dst, const void* src) {
    asm volatile("cp.async.ca.shared.global [%0], [%1], 16;\n" :: "r"(dst), "l"(src));
}
__device__ __forceinline__ void cp_commit() {
    asm volatile("cp.async.commit_group;\n" ::: "memory");
}
template <int N>
__device__ __forceinline__ void cp_wait() {
    asm volatile("cp.async.wait_group %0;\n" :: "n"(N) : "memory");
}

// exact hi/lo split: hi = v with low 13 mantissa bits cleared (valid tf32), lo = v - hi (exact)
__device__ __forceinline__ float tf_hi(float v) {
    return __uint_as_float(__float_as_uint(v) & 0xFFFFE000u);
}
__device__ __forceinline__ uint32_t rn_tf32(float f) {
    uint32_t r; asm("cvt.rna.tf32.f32 %0, %1;" : "=r"(r) : "f"(f)); return r;
}

// D = A(16x8,row) * B(8x8,col) + D, tf32 inputs, fp32 accum
__device__ __forceinline__ void mma8(float* c, const uint32_t* a, const uint32_t* b) {
    asm volatile(
        "mma.sync.aligned.m16n8k8.row.col.f32.tf32.tf32.f32 "
        "{%0,%1,%2,%3}, {%4,%5,%6,%7}, {%8,%9}, {%0,%1,%2,%3};\n"
        : "+f"(c[0]), "+f"(c[1]), "+f"(c[2]), "+f"(c[3])
        : "r"(a[0]), "r"(a[1]), "r"(a[2]), "r"(a[3]),
          "r"(b[0]), "r"(b[1]));
}

// Dynamic smem layout (floats):
//   [0,     4352)  x chunk stage 0 / proj / Wh
//   [4352,  8704)  x chunk stage 1 / Wl
//   [8704, 13312)  B chunk stage 0 (phase A: 64*SA used; phase C: 64*SC=4608)
//   [13312,17920)  B chunk stage 1
#define SMEM_FLOATS 17920
#define SMEM_BYTES (SMEM_FLOATS * 4)

__global__ __launch_bounds__(THREADS, 2) void afd_kernel(
    const float* __restrict__ x, float* __restrict__ out)
{
    extern __shared__ float sm[];
    const int tid  = threadIdx.x;
    const int warp = tid >> 5;
    const int lane = tid & 31;
    const int g    = lane >> 2;
    const int tig  = lane & 3;
    const int row0 = blockIdx.x * ROWS_CTA;

    float* sX0 = sm;
    float* sX1 = sm + 4352;
    float* sB0 = sm + 8704;
    float* sB1 = sm + 13312;

    // ---------------- Phase A: proj[basis, row] = sum_l B[basis,l]*x[row,l] (3xTF32 split)
    {
        const int bas0 = (warp & 3) * 16;   // 16 basis rows per warp tile
        const int ro0  = (warp >> 2) * 32;  // 32 data rows per warp tile

        float acc[4][4];
        #pragma unroll
        for (int i = 0; i < 4; i++)
            #pragma unroll
            for (int j = 0; j < 4; j++) acc[i][j] = 0.f;

        // prologue: issue chunk 0
        {
            float* dx = sX0; float* db = sB0;
            #pragma unroll
            for (int i = 0; i < 4; i++) {
                int idx = tid + i * 256; int r = idx >> 4, q = idx & 15;
                cp16(smem_u32(dx + r * SA + q * 4), x + (size_t)(row0 + r) * LVAL + q * 4);
                cp16(smem_u32(db + r * SA + q * 4), g_B + (size_t)r * LVAL + q * 4);
            }
            cp_commit();
        }

        for (int c = 0; c < NCHUNK; c++) {
            if (c + 1 < NCHUNK) {
                int k0 = (c + 1) * KC;
                float* dx = ((c + 1) & 1) ? sX1 : sX0;
                float* db = ((c + 1) & 1) ? sB1 : sB0;
                #pragma unroll
                for (int i = 0; i < 4; i++) {
                    int idx = tid + i * 256; int r = idx >> 4, q = idx & 15;
                    cp16(smem_u32(dx + r * SA + q * 4), x + (size_t)(row0 + r) * LVAL + k0 + q * 4);
                    cp16(smem_u32(db + r * SA + q * 4), g_B + (size_t)r * LVAL + k0 + q * 4);
                }
                cp_commit();
                cp_wait<1>();
            } else {
                cp_wait<0>();
            }
            __syncthreads();

            const float* bx = (c & 1) ? sX1 : sX0;
            const float* bb = (c & 1) ? sB1 : sB0;

            #pragma unroll
            for (int kk = 0; kk < KC; kk += 8) {
                const float* ap = bb + (bas0 + g) * SA + kk + tig;
                float ar0 = ap[0], ar1 = ap[8 * SA], ar2 = ap[4], ar3 = ap[8 * SA + 4];
                float h0 = tf_hi(ar0), h1 = tf_hi(ar1), h2 = tf_hi(ar2), h3 = tf_hi(ar3);
                uint32_t ah[4] = { __float_as_uint(h0), __float_as_uint(h1),
                                   __float_as_uint(h2), __float_as_uint(h3) };
                uint32_t al[4] = { __float_as_uint(ar0 - h0), __float_as_uint(ar1 - h1),
                                   __float_as_uint(ar2 - h2), __float_as_uint(ar3 - h3) };
                #pragma unroll
                for (int nt = 0; nt < 4; nt++) {
                    const float* bp = bx + (ro0 + nt * 8 + g) * SA + kk + tig;
                    float b0 = bp[0], b1 = bp[4];
                    float bh0 = tf_hi(b0), bh1 = tf_hi(b1);
                    uint32_t bh[2] = { __float_as_uint(bh0), __float_as_uint(bh1) };
                    uint32_t bl[2] = { __float_as_uint(b0 - bh0), __float_as_uint(b1 - bh1) };
                    mma8(acc[nt], ah, bh);
                    mma8(acc[nt], ah, bl);
                    mma8(acc[nt], al, bh);
                }
            }
            __syncthreads();
        }

        // ---------------- Phase B: dump proj -> smem [row][basis], softmax(|.|), split W
        #pragma unroll
        for (int nt = 0; nt < 4; nt++) {
            int rr = ro0 + nt * 8 + 2 * tig;
            int bs = bas0 + g;
            sm[rr * SA + bs]           = acc[nt][0];
            sm[(rr + 1) * SA + bs]     = acc[nt][1];
            sm[rr * SA + bs + 8]       = acc[nt][2];
            sm[(rr + 1) * SA + bs + 8] = acc[nt][3];
        }
    }
    __syncthreads();

    {
        float* sWh = sX0;  // in-place over proj
        float* sWl = sX1;
        for (int r = warp * 8; r < warp * 8 + 8; r++) {
            float v0 = fabsf(sm[r * SA + lane]);
            float v1 = fabsf(sm[r * SA + lane + 32]);
            float m = fmaxf(v0, v1);
            #pragma unroll
            for (int o = 16; o > 0; o >>= 1) m = fmaxf(m, __shfl_xor_sync(0xffffffffu, m, o));
            float e0 = __expf(v0 - m), e1 = __expf(v1 - m);
            float s = e0 + e1;
            #pragma unroll
            for (int o = 16; o > 0; o >>= 1) s += __shfl_xor_sync(0xffffffffu, s, o);
            float inv = 1.0f / s;
            float w0 = e0 * inv, w1 = e1 * inv;
            float h0 = tf_hi(w0), h1 = tf_hi(w1);
            sWh[r * SA + lane]      = h0;
            sWl[r * SA + lane]      = w0 - h0;
            sWh[r * SA + lane + 32] = h1;
            sWl[r * SA + lane + 32] = w1 - h1;
        }
    }
    __syncthreads();

    // ---------------- Phase C: out[row,l] = x[row,l] + sum_n W[row,n]*B[n,l] (W split)
    {
        const float* sWh = sX0;
        const float* sWl = sX1;
        const int r0  = (warp & 3) * 16;   // 16 output rows per warp tile
        const int lo0 = (warp >> 2) * 32;  // 32 l-columns per warp tile

        // prologue: issue chunk 0
        {
            #pragma unroll
            for (int i = 0; i < 4; i++) {
                int idx = tid + i * 256; int n = idx >> 4, q = idx & 15;
                cp16(smem_u32(sB0 + n * SC + q * 4), g_B + (size_t)n * LVAL + q * 4);
            }
            cp_commit();
        }

        for (int c = 0; c < NCHUNK; c++) {
            if (c + 1 < NCHUNK) {
                int l0n = (c + 1) * KC;
                float* db = ((c + 1) & 1) ? sB1 : sB0;
                #pragma unroll
                for (int i = 0; i < 4; i++) {
                    int idx = tid + i * 256; int n = idx >> 4, q = idx & 15;
                    cp16(smem_u32(db + n * SC + q * 4), g_B + (size_t)n * LVAL + l0n + q * 4);
                }
                cp_commit();
                cp_wait<1>();
            } else {
                cp_wait<0>();
            }
            __syncthreads();

            const float* bc = (c & 1) ? sB1 : sB0;

            float acc[4][4];
            #pragma unroll
            for (int i = 0; i < 4; i++)
                #pragma unroll
                for (int j = 0; j < 4; j++) acc[i][j] = 0.f;

            #pragma unroll
            for (int kk = 0; kk < NB; kk += 8) {
                const float* hp = sWh + (r0 + g) * SA + kk + tig;
                const float* lp = sWl + (r0 + g) * SA + kk + tig;
                uint32_t ah[4] = { __float_as_uint(hp[0]), __float_as_uint(hp[8 * SA]),
                                   __float_as_uint(hp[4]), __float_as_uint(hp[8 * SA + 4]) };
                uint32_t al[4] = { __float_as_uint(lp[0]), __float_as_uint(lp[8 * SA]),
                                   __float_as_uint(lp[4]), __float_as_uint(lp[8 * SA + 4]) };
                #pragma unroll
                for (int nt = 0; nt < 4; nt++) {
                    const float* bp = bc + (kk + tig) * SC + lo0 + nt * 8 + g;
                    uint32_t b[2] = { rn_tf32(bp[0]), rn_tf32(bp[4 * SC]) };
                    mma8(acc[nt], ah, b);
                    mma8(acc[nt], al, b);
                }
            }
            __syncthreads();   // all warps done with bc before next iter's cp.async reuses it

            // epilogue: out = x + attn
            int l0 = c * KC;
            #pragma unroll
            for (int nt = 0; nt < 4; nt++) {
                int row = row0 + r0 + g;
                int lc  = l0 + lo0 + nt * 8 + 2 * tig;
                size_t i0 = (size_t)row * LVAL + lc;
                float2 xv = *(const float2*)(x + i0);
                *(float2*)(out + i0) = make_float2(xv.x + acc[nt][0], xv.y + acc[nt][1]);
                size_t i1 = i0 + (size_t)8 * LVAL;
                float2 xw = *(const float2*)(x + i1);
                *(float2*)(out + i1) = make_float2(xw.x + acc[nt][2], xw.y + acc[nt][3]);
            }
        }
    }
}

extern "C" void kernel_launch(void* const* d_in, const int* in_sizes, int n_in,
                              void* d_out, int out_size) {
    const float* x = (const float*)d_in[0];
    float* out = (float*)d_out;
    (void)in_sizes; (void)n_in; (void)out_size;

    cudaFuncSetAttribute(afd_kernel, cudaFuncAttributeMaxDynamicSharedMemorySize, SMEM_BYTES);
    build_B_kernel<<<(NB * LVAL + 255) / 256, 256>>>();
    afd_kernel<<<16384 / ROWS_CTA, THREADS, SMEM_BYTES>>>(x, out);
}

// round 7
// speedup vs baseline: 1.4744x; 1.3854x over previous
#include <cuda_runtime.h>
#include <cuda_fp16.h>
#include <cstdint>

#define LVAL 4096
#define NB 64
#define NROWS 16384            // 32*512
#define PW 36                  // padded row stride in u32 words (32 data words + 4 pad)
#define RADIUS 0.9

// ---------------- device globals (no allocs allowed) ----------------
__device__ __half g_Bh [NB * LVAL];    // Blaschke hi split, [n][l] l-contig
__device__ __half g_Bl [NB * LVAL];    // lo split
__device__ __half g_BTh[LVAL * NB];    // transposed hi split, [l][n] n-contig
__device__ __half g_BTl[LVAL * NB];
__device__ float  g_proj[4 * NROWS * NB];   // split-K partial projections (4 slabs)
__device__ __half g_W0[NROWS * NB];    // softmax weights hi split, [row][n]
__device__ __half g_W1[NROWS * NB];    // lo split

// ---------------- helpers ----------------
__device__ __forceinline__ unsigned smem_u32p(const void* p) {
    return (unsigned)__cvta_generic_to_shared(p);
}
__device__ __forceinline__ void cp16(unsigned dst, const void* src) {
    asm volatile("cp.async.ca.shared.global [%0], [%1], 16;\n" :: "r"(dst), "l"(src));
}
__device__ __forceinline__ void cp_commit() {
    asm volatile("cp.async.commit_group;\n" ::: "memory");
}
template <int N>
__device__ __forceinline__ void cp_wait() {
    asm volatile("cp.async.wait_group %0;\n" :: "n"(N) : "memory");
}
__device__ __forceinline__ uint32_t packh(__half a, __half b) {
    __half2 h = __halves2half2(a, b);
    return *reinterpret_cast<uint32_t*>(&h);
}
__device__ __forceinline__ uint32_t pack_rn(float a, float b) {
    return packh(__float2half_rn(a), __float2half_rn(b));
}

// D(16x8) += A(16x16) * B(16x8), fp16 inputs, fp32 accum
__device__ __forceinline__ void mma16(float* c, const uint32_t* a, const uint32_t* b) {
    asm volatile(
        "mma.sync.aligned.m16n8k16.row.col.f32.f16.f16.f32 "
        "{%0,%1,%2,%3}, {%4,%5,%6,%7}, {%8,%9}, {%0,%1,%2,%3};\n"
        : "+f"(c[0]), "+f"(c[1]), "+f"(c[2]), "+f"(c[3])
        : "r"(a[0]), "r"(a[1]), "r"(a[2]), "r"(a[3]),
          "r"(b[0]), "r"(b[1]));
}

// ---------------- k1: build Blaschke basis + fp16 splits ----------------
__global__ void k1_build() {
    int idx = blockIdx.x * blockDim.x + threadIdx.x;
    if (idx >= NB * LVAL) return;
    int n = idx >> 12;
    int l = idx & 4095;
    const double TWO_PI = 6.283185307179586476925286766559;
    double theta = (double)n * (TWO_PI / 64.0);
    double t     = (double)l * (TWO_PI / 4095.0);   // linspace(0,2pi,4096) incl. endpoint
    double c = cos(t - theta);
    const double r = RADIUS;
    double val = sqrt(1.0 - r * r) * (1.0 - r * c) / (1.0 - 2.0 * r * c + r * r);
    float v = (float)val;
    __half h = __float2half_rn(v);
    __half lo = __float2half_rn(v - __half2float(h));
    g_Bh [n * LVAL + l] = h;
    g_Bl [n * LVAL + l] = lo;
    g_BTh[l * NB + n]   = h;
    g_BTl[l * NB + n]   = lo;
}

// ---------------- k2: proj slab GEMM  (split-K = 4) ----------------
// CTA: 64 rows x 64 basis, K-slice 1024, chunks of 64.
// smem stage (u32 words): xh[0,2304) xl[2304,4608) bh[4608,6912) bl[6912,9216); 2 stages.
#define K2_STAGE 9216
#define K2_SMEM_BYTES (2 * K2_STAGE * 4)

__global__ __launch_bounds__(256, 3) void k2_proj(const float* __restrict__ x) {
    extern __shared__ uint32_t smu[];
    const int tid = threadIdx.x, warp = tid >> 5, lane = tid & 31;
    const int g = lane >> 2, tig = lane & 3;
    const int r0 = blockIdx.x * 64;
    const int kb0 = blockIdx.y * 1024;
    const int rw = (warp & 3) * 16;      // warp row offset
    const int nw = (warp >> 2) * 32;     // warp basis offset
    const int quad = tid & 15, rloc = tid >> 4;

    float acc[4][4];
    #pragma unroll
    for (int i = 0; i < 4; i++)
        #pragma unroll
        for (int j = 0; j < 4; j++) acc[i][j] = 0.f;

    auto stage = [&](int c) {
        uint32_t* b = smu + (c & 1) * K2_STAGE;
        const int kbase = kb0 + c * 64;
        // B splits via cp.async (fp16 in gmem already)
        #pragma unroll
        for (int j = 0; j < 2; j++) {
            int e = tid + j * 256; int row = e >> 3, seg = e & 7;
            cp16(smem_u32p(b + 4608 + row * PW + seg * 4),
                 g_Bh + (size_t)row * LVAL + kbase + seg * 8);
            cp16(smem_u32p(b + 6912 + row * PW + seg * 4),
                 g_Bl + (size_t)row * LVAL + kbase + seg * 8);
        }
        cp_commit();
        // x: LDG fp32 -> split -> STS fp16
        #pragma unroll
        for (int i = 0; i < 4; i++) {
            int row = rloc + i * 16;
            const float4 v = *(const float4*)(x + (size_t)(r0 + row) * LVAL + kbase + quad * 4);
            __half hx = __float2half_rn(v.x), hy = __float2half_rn(v.y);
            __half hz = __float2half_rn(v.z), hw = __float2half_rn(v.w);
            uint32_t h01 = packh(hx, hy), h23 = packh(hz, hw);
            uint32_t l01 = pack_rn(v.x - __half2float(hx), v.y - __half2float(hy));
            uint32_t l23 = pack_rn(v.z - __half2float(hz), v.w - __half2float(hw));
            *(uint2*)(b + row * PW + quad * 2)        = make_uint2(h01, h23);
            *(uint2*)(b + 2304 + row * PW + quad * 2) = make_uint2(l01, l23);
        }
    };

    stage(0);
    for (int c = 0; c < 16; c++) {
        if (c + 1 < 16) { stage(c + 1); cp_wait<1>(); }
        else            { cp_wait<0>(); }
        __syncthreads();

        const uint32_t* buf = smu + (c & 1) * K2_STAGE;
        #pragma unroll
        for (int ks = 0; ks < 4; ks++) {
            const int k8 = ks * 8;
            const uint32_t* ap = buf + (rw + g) * PW + k8 + tig;
            uint32_t ah[4] = { ap[0], ap[8 * PW], ap[4], ap[8 * PW + 4] };
            uint32_t al[4] = { ap[2304], ap[2304 + 8 * PW], ap[2304 + 4], ap[2304 + 8 * PW + 4] };
            #pragma unroll
            for (int nt = 0; nt < 4; nt++) {
                const uint32_t* bp = buf + 4608 + (nw + nt * 8 + g) * PW + k8 + tig;
                uint32_t bh[2] = { bp[0], bp[4] };
                uint32_t bl[2] = { bp[2304], bp[2304 + 4] };
                mma16(acc[nt], ah, bh);
                mma16(acc[nt], ah, bl);
                mma16(acc[nt], al, bh);
            }
        }
        __syncthreads();
    }

    float* slab = g_proj + (size_t)blockIdx.y * (NROWS * NB);
    #pragma unroll
    for (int nt = 0; nt < 4; nt++) {
        int col = nw + nt * 8 + 2 * tig;
        int row = r0 + rw + g;
        *(float2*)(slab + (size_t)row * NB + col)       = make_float2(acc[nt][0], acc[nt][1]);
        *(float2*)(slab + (size_t)(row + 8) * NB + col) = make_float2(acc[nt][2], acc[nt][3]);
    }
}

// ---------------- k3: reduce slabs + softmax(|.|) + fp16 W split ----------------
__global__ __launch_bounds__(256) void k3_softmax() {
    const int warp = threadIdx.x >> 5, lane = threadIdx.x & 31;
    const int row = blockIdx.x * 8 + warp;
    const size_t base = (size_t)row * NB + 2 * lane;
    float p0 = 0.f, p1 = 0.f;
    #pragma unroll
    for (int s = 0; s < 4; s++) {
        float2 v = *(const float2*)(g_proj + (size_t)s * (NROWS * NB) + base);
        p0 += v.x; p1 += v.y;
    }
    float a0 = fabsf(p0), a1 = fabsf(p1);
    float m = fmaxf(a0, a1);
    #pragma unroll
    for (int o = 16; o > 0; o >>= 1) m = fmaxf(m, __shfl_xor_sync(0xffffffffu, m, o));
    float e0 = __expf(a0 - m), e1 = __expf(a1 - m);
    float s = e0 + e1;
    #pragma unroll
    for (int o = 16; o > 0; o >>= 1) s += __shfl_xor_sync(0xffffffffu, s, o);
    float inv = 1.0f / s;
    float w0 = e0 * inv, w1 = e1 * inv;
    __half h0 = __float2half_rn(w0), h1 = __float2half_rn(w1);
    *(uint32_t*)&g_W0[base] = packh(h0, h1);
    *(uint32_t*)&g_W1[base] = pack_rn(w0 - __half2float(h0), w1 - __half2float(h1));
}

// ---------------- k4: out = x + W*B  (64 rows x 64 l per CTA) ----------------
// smem (u32 words): wh[0,2304) wl[2304,4608) bth[4608,6912) btl[6912,9216)
#define K4_SMEM_BYTES (9216 * 4)

__global__ __launch_bounds__(256, 3) void k4_attn(
    const float* __restrict__ x, float* __restrict__ out)
{
    extern __shared__ uint32_t smu[];
    const int tid = threadIdx.x, warp = tid >> 5, lane = tid & 31;
    const int g = lane >> 2, tig = lane & 3;
    const int r0 = blockIdx.y * 64;
    const int l0 = blockIdx.x * 64;
    const int rw = (warp & 3) * 16;      // warp row offset
    const int lw = (warp >> 2) * 32;     // warp l offset

    #pragma unroll
    for (int j = 0; j < 2; j++) {
        int e = tid + j * 256; int row = e >> 3, seg = e & 7;
        cp16(smem_u32p(smu + 0    + row * PW + seg * 4), g_W0  + (size_t)(r0 + row) * NB + seg * 8);
        cp16(smem_u32p(smu + 2304 + row * PW + seg * 4), g_W1  + (size_t)(r0 + row) * NB + seg * 8);
        cp16(smem_u32p(smu + 4608 + row * PW + seg * 4), g_BTh + (size_t)(l0 + row) * NB + seg * 8);
        cp16(smem_u32p(smu + 6912 + row * PW + seg * 4), g_BTl + (size_t)(l0 + row) * NB + seg * 8);
    }
    cp_commit();
    cp_wait<0>();
    __syncthreads();

    float acc[4][4];
    #pragma unroll
    for (int i = 0; i < 4; i++)
        #pragma unroll
        for (int j = 0; j < 4; j++) acc[i][j] = 0.f;

    #pragma unroll
    for (int ks = 0; ks < 4; ks++) {
        const int k8 = ks * 8;
        const uint32_t* ap = smu + (rw + g) * PW + k8 + tig;
        uint32_t ah[4] = { ap[0], ap[8 * PW], ap[4], ap[8 * PW + 4] };
        uint32_t al[4] = { ap[2304], ap[2304 + 8 * PW], ap[2304 + 4], ap[2304 + 8 * PW + 4] };
        #pragma unroll
        for (int nt = 0; nt < 4; nt++) {
            const uint32_t* bp = smu + 4608 + (lw + nt * 8 + g) * PW + k8 + tig;
            uint32_t bh[2] = { bp[0], bp[4] };
            uint32_t bl[2] = { bp[2304], bp[2304 + 4] };
            mma16(acc[nt], ah, bh);
            mma16(acc[nt], ah, bl);
            mma16(acc[nt], al, bh);
        }
    }

    #pragma unroll
    for (int nt = 0; nt < 4; nt++) {
        int row = r0 + rw + g;
        int l   = l0 + lw + nt * 8 + 2 * tig;
        size_t i0 = (size_t)row * LVAL + l;
        float2 xv = *(const float2*)(x + i0);
        *(float2*)(out + i0) = make_float2(xv.x + acc[nt][0], xv.y + acc[nt][1]);
        size_t i1 = i0 + (size_t)8 * LVAL;
        float2 xw = *(const float2*)(x + i1);
        *(float2*)(out + i1) = make_float2(xw.x + acc[nt][2], xw.y + acc[nt][3]);
    }
}

// ---------------- launch ----------------
extern "C" void kernel_launch(void* const* d_in, const int* in_sizes, int n_in,
                              void* d_out, int out_size) {
    const float* x = (const float*)d_in[0];
    float* out = (float*)d_out;
    (void)in_sizes; (void)n_in; (void)out_size;

    static bool attr_done = false;
    if (!attr_done) {
        cudaFuncSetAttribute(k2_proj, cudaFuncAttributeMaxDynamicSharedMemorySize, K2_SMEM_BYTES);
        cudaFuncSetAttribute(k4_attn, cudaFuncAttributeMaxDynamicSharedMemorySize, K4_SMEM_BYTES);
        attr_done = true;
    }

    k1_build<<<(NB * LVAL + 255) / 256, 256>>>();
    k2_proj<<<dim3(NROWS / 64, 4), 256, K2_SMEM_BYTES>>>(x);
    k3_softmax<<<NROWS / 8, 256>>>();
    k4_attn<<<dim3(LVAL / 64, NROWS / 64), 256, K4_SMEM_BYTES>>>(x, out);
}

// round 8
// speedup vs baseline: 1.5858x; 1.0755x over previous
#include <cuda_runtime.h>
#include <cuda_fp16.h>
#include <cstdint>

#define LVAL 4096
#define NB 64
#define NROWS 16384            // 32*512
#define PW 36                  // padded row stride in u32 words (32 data words + 4 pad)
#define RADIUS 0.9

// ---------------- device globals (no allocs allowed) ----------------
__device__ __half g_Bh [NB * LVAL];    // Blaschke hi split, [n][l] l-contig
__device__ __half g_Bl [NB * LVAL];    // lo split
__device__ __half g_BTh[LVAL * NB];    // transposed hi split, [l][n] n-contig
__device__ __half g_BTl[LVAL * NB];
__device__ float  g_proj[4 * NROWS * NB];   // split-K partial projections (4 slabs)
__device__ __half g_W0[NROWS * NB];    // softmax weights hi split, [row][n]
__device__ __half g_W1[NROWS * NB];    // lo split

// ---------------- helpers ----------------
__device__ __forceinline__ unsigned smem_u32p(const void* p) {
    return (unsigned)__cvta_generic_to_shared(p);
}
__device__ __forceinline__ void cp16(unsigned dst, const void* src) {
    asm volatile("cp.async.ca.shared.global [%0], [%1], 16;\n" :: "r"(dst), "l"(src));
}
__device__ __forceinline__ void cp_commit() {
    asm volatile("cp.async.commit_group;\n" ::: "memory");
}
template <int N>
__device__ __forceinline__ void cp_wait() {
    asm volatile("cp.async.wait_group %0;\n" :: "n"(N) : "memory");
}
__device__ __forceinline__ uint32_t packh(__half a, __half b) {
    __half2 h = __halves2half2(a, b);
    return *reinterpret_cast<uint32_t*>(&h);
}
__device__ __forceinline__ uint32_t pack_rn(float a, float b) {
    return packh(__float2half_rn(a), __float2half_rn(b));
}

// D(16x8) += A(16x16) * B(16x8), fp16 inputs, fp32 accum
__device__ __forceinline__ void mma16(float* c, const uint32_t* a, const uint32_t* b) {
    asm volatile(
        "mma.sync.aligned.m16n8k16.row.col.f32.f16.f16.f32 "
        "{%0,%1,%2,%3}, {%4,%5,%6,%7}, {%8,%9}, {%0,%1,%2,%3};\n"
        : "+f"(c[0]), "+f"(c[1]), "+f"(c[2]), "+f"(c[3])
        : "r"(a[0]), "r"(a[1]), "r"(a[2]), "r"(a[3]),
          "r"(b[0]), "r"(b[1]));
}

__device__ __forceinline__ void ldsm_x4(uint32_t* r, uint32_t addr) {
    asm volatile("ldmatrix.sync.aligned.m8n8.x4.shared.b16 {%0,%1,%2,%3}, [%4];"
        : "=r"(r[0]), "=r"(r[1]), "=r"(r[2]), "=r"(r[3]) : "r"(addr));
}

// ---------------- k1: build Blaschke basis + fp16 splits ----------------
__global__ void k1_build() {
    int idx = blockIdx.x * blockDim.x + threadIdx.x;
    if (idx >= NB * LVAL) return;
    int n = idx >> 12;
    int l = idx & 4095;
    const double TWO_PI = 6.283185307179586476925286766559;
    double theta = (double)n * (TWO_PI / 64.0);
    double t     = (double)l * (TWO_PI / 4095.0);   // linspace(0,2pi,4096) incl. endpoint
    double c = cos(t - theta);
    const double r = RADIUS;
    double val = sqrt(1.0 - r * r) * (1.0 - r * c) / (1.0 - 2.0 * r * c + r * r);
    float v = (float)val;
    __half h = __float2half_rn(v);
    __half lo = __float2half_rn(v - __half2float(h));
    g_Bh [n * LVAL + l] = h;
    g_Bl [n * LVAL + l] = lo;
    g_BTh[l * NB + n]   = h;
    g_BTl[l * NB + n]   = lo;
}

// ---------------- k2: proj slab GEMM  (split-K = 4) ----------------
// CTA: 64 rows x 64 basis, K-slice 1024, chunks of 64.
// smem stage (u32 words): xh[0,2304) xl[2304,4608) bh[4608,6912) bl[6912,9216); 2 stages.
#define K2_STAGE 9216
#define K2_SMEM_BYTES (2 * K2_STAGE * 4)

__global__ __launch_bounds__(256, 3) void k2_proj(const float* __restrict__ x) {
    extern __shared__ uint32_t smu[];
    const int tid = threadIdx.x, warp = tid >> 5, lane = tid & 31;
    const int g = lane >> 2, tig = lane & 3;
    const int r0 = blockIdx.x * 64;
    const int kb0 = blockIdx.y * 1024;
    const int rw = (warp & 3) * 16;      // warp row offset
    const int nw = (warp >> 2) * 32;     // warp basis offset
    const int quad = tid & 15, rloc = tid >> 4;

    float acc[4][4];
    #pragma unroll
    for (int i = 0; i < 4; i++)
        #pragma unroll
        for (int j = 0; j < 4; j++) acc[i][j] = 0.f;

    auto stage = [&](int c) {
        uint32_t* b = smu + (c & 1) * K2_STAGE;
        const int kbase = kb0 + c * 64;
        #pragma unroll
        for (int j = 0; j < 2; j++) {
            int e = tid + j * 256; int row = e >> 3, seg = e & 7;
            cp16(smem_u32p(b + 4608 + row * PW + seg * 4),
                 g_Bh + (size_t)row * LVAL + kbase + seg * 8);
            cp16(smem_u32p(b + 6912 + row * PW + seg * 4),
                 g_Bl + (size_t)row * LVAL + kbase + seg * 8);
        }
        cp_commit();
        #pragma unroll
        for (int i = 0; i < 4; i++) {
            int row = rloc + i * 16;
            const float4 v = *(const float4*)(x + (size_t)(r0 + row) * LVAL + kbase + quad * 4);
            __half hx = __float2half_rn(v.x), hy = __float2half_rn(v.y);
            __half hz = __float2half_rn(v.z), hw = __float2half_rn(v.w);
            uint32_t h01 = packh(hx, hy), h23 = packh(hz, hw);
            uint32_t l01 = pack_rn(v.x - __half2float(hx), v.y - __half2float(hy));
            uint32_t l23 = pack_rn(v.z - __half2float(hz), v.w - __half2float(hw));
            *(uint2*)(b + row * PW + quad * 2)        = make_uint2(h01, h23);
            *(uint2*)(b + 2304 + row * PW + quad * 2) = make_uint2(l01, l23);
        }
    };

    stage(0);
    for (int c = 0; c < 16; c++) {
        if (c + 1 < 16) { stage(c + 1); cp_wait<1>(); }
        else            { cp_wait<0>(); }
        __syncthreads();

        const uint32_t* buf = smu + (c & 1) * K2_STAGE;
        #pragma unroll
        for (int ks = 0; ks < 4; ks++) {
            const int k8 = ks * 8;
            const uint32_t* ap = buf + (rw + g) * PW + k8 + tig;
            uint32_t ah[4] = { ap[0], ap[8 * PW], ap[4], ap[8 * PW + 4] };
            uint32_t al[4] = { ap[2304], ap[2304 + 8 * PW], ap[2304 + 4], ap[2304 + 8 * PW + 4] };
            #pragma unroll
            for (int nt = 0; nt < 4; nt++) {
                const uint32_t* bp = buf + 4608 + (nw + nt * 8 + g) * PW + k8 + tig;
                uint32_t bh[2] = { bp[0], bp[4] };
                uint32_t bl[2] = { bp[2304], bp[2304 + 4] };
                mma16(acc[nt], ah, bh);
                mma16(acc[nt], ah, bl);
                mma16(acc[nt], al, bh);
            }
        }
        __syncthreads();
    }

    float* slab = g_proj + (size_t)blockIdx.y * (NROWS * NB);
    #pragma unroll
    for (int nt = 0; nt < 4; nt++) {
        int col = nw + nt * 8 + 2 * tig;
        int row = r0 + rw + g;
        *(float2*)(slab + (size_t)row * NB + col)       = make_float2(acc[nt][0], acc[nt][1]);
        *(float2*)(slab + (size_t)(row + 8) * NB + col) = make_float2(acc[nt][2], acc[nt][3]);
    }
}

// ---------------- k3: reduce slabs + softmax(|.|) + fp16 W split ----------------
__global__ __launch_bounds__(256) void k3_softmax() {
    const int warp = threadIdx.x >> 5, lane = threadIdx.x & 31;
    const int row = blockIdx.x * 8 + warp;
    const size_t base = (size_t)row * NB + 2 * lane;
    float p0 = 0.f, p1 = 0.f;
    #pragma unroll
    for (int s = 0; s < 4; s++) {
        float2 v = *(const float2*)(g_proj + (size_t)s * (NROWS * NB) + base);
        p0 += v.x; p1 += v.y;
    }
    float a0 = fabsf(p0), a1 = fabsf(p1);
    float m = fmaxf(a0, a1);
    #pragma unroll
    for (int o = 16; o > 0; o >>= 1) m = fmaxf(m, __shfl_xor_sync(0xffffffffu, m, o));
    float e0 = __expf(a0 - m), e1 = __expf(a1 - m);
    float s = e0 + e1;
    #pragma unroll
    for (int o = 16; o > 0; o >>= 1) s += __shfl_xor_sync(0xffffffffu, s, o);
    float inv = 1.0f / s;
    float w0 = e0 * inv, w1 = e1 * inv;
    __half h0 = __float2half_rn(w0), h1 = __float2half_rn(w1);
    *(uint32_t*)&g_W0[base] = packh(h0, h1);
    *(uint32_t*)&g_W1[base] = pack_rn(w0 - __half2float(h0), w1 - __half2float(h1));
}

// ---------------- k4: out = x + W*B  (64 rows x 128 l per CTA, ldmatrix frags) ----------------
// smem (u32 words): Wh[0,2304) Wl[2304,4608) BTh[4608,9216) BTl[9216,13824)
#define K4_SMEM_WORDS 13824
#define K4_SMEM_BYTES (K4_SMEM_WORDS * 4)

__global__ __launch_bounds__(256, 3) void k4_attn(
    const float* __restrict__ x, float* __restrict__ out)
{
    extern __shared__ uint32_t smu[];
    const int tid = threadIdx.x, warp = tid >> 5, lane = tid & 31;
    const int g = lane >> 2, tig = lane & 3;
    const int r0 = blockIdx.y * 64;
    const int l0 = blockIdx.x * 128;
    const int rw = (warp & 1) * 32;      // warp row offset (2 groups of 32)
    const int lw = (warp >> 1) * 32;     // warp l offset   (4 groups of 32)

    // -------- stage W (64 rows) and BT (128 rows) hi/lo via cp.async --------
    #pragma unroll
    for (int j = 0; j < 2; j++) {
        int e = tid + j * 256; int row = e >> 3, seg = e & 7;
        cp16(smem_u32p(smu + 0    + row * PW + seg * 4), g_W0 + (size_t)(r0 + row) * NB + seg * 8);
        cp16(smem_u32p(smu + 2304 + row * PW + seg * 4), g_W1 + (size_t)(r0 + row) * NB + seg * 8);
    }
    #pragma unroll
    for (int j = 0; j < 4; j++) {
        int e = tid + j * 256; int row = e >> 3, seg = e & 7;
        cp16(smem_u32p(smu + 4608 + row * PW + seg * 4), g_BTh + (size_t)(l0 + row) * NB + seg * 8);
        cp16(smem_u32p(smu + 9216 + row * PW + seg * 4), g_BTl + (size_t)(l0 + row) * NB + seg * 8);
    }
    cp_commit();
    cp_wait<0>();
    __syncthreads();

    // -------- per-lane ldmatrix base addresses --------
    // A (16x16 tile, x4): tile order a0(r0-7,klo) a1(r8-15,klo) a2(r0-7,khi) a3(r8-15,khi)
    const int arow  = (lane & 7) | (lane & 8);       // 0..15
    const int acol16 = (lane >> 4) & 1;              // 0/1 -> +16B
    const uint32_t aHi = smem_u32p(smu +        (rw + arow) * PW) + acol16 * 16;
    const uint32_t aLo = smem_u32p(smu + 2304 + (rw + arow) * PW) + acol16 * 16;
    // B (two 16x8 n-tiles per x4): tiles b0(nt,klo) b1(nt,khi) b0(nt+1,klo) b1(nt+1,khi)
    const int brow  = lane & 7;
    const int bcol16 = (lane >> 3) & 1;
    const int bpair = (lane >> 4) & 1;               // second nt of pair
    const uint32_t bHi = smem_u32p(smu + 4608 + (lw + bpair * 8 + brow) * PW) + bcol16 * 16;
    const uint32_t bLo = smem_u32p(smu + 9216 + (lw + bpair * 8 + brow) * PW) + bcol16 * 16;

    float acc[8][4];
    #pragma unroll
    for (int i = 0; i < 8; i++)
        #pragma unroll
        for (int j = 0; j < 4; j++) acc[i][j] = 0.f;

    #pragma unroll
    for (int ks = 0; ks < 4; ks++) {
        const int kb = ks * 32;   // 16 halfs = 32 bytes per k-step
        uint32_t ah[2][4], al[2][4], bh[2][4], bl[2][4];
        #pragma unroll
        for (int mt = 0; mt < 2; mt++) {
            ldsm_x4(ah[mt], aHi + mt * (16 * PW * 4) + kb);
            ldsm_x4(al[mt], aLo + mt * (16 * PW * 4) + kb);
        }
        #pragma unroll
        for (int p = 0; p < 2; p++) {
            ldsm_x4(bh[p], bHi + p * (16 * PW * 4) + kb);
            ldsm_x4(bl[p], bLo + p * (16 * PW * 4) + kb);
        }
        #pragma unroll
        for (int mt = 0; mt < 2; mt++)
            #pragma unroll
            for (int nt = 0; nt < 4; nt++) {
                const int p = nt >> 1, o = (nt & 1) * 2;
                mma16(acc[mt * 4 + nt], ah[mt], &bh[p][o]);
                mma16(acc[mt * 4 + nt], ah[mt], &bl[p][o]);
                mma16(acc[mt * 4 + nt], al[mt], &bh[p][o]);
            }
    }

    // -------- epilogue: out = x + attn --------
    #pragma unroll
    for (int mt = 0; mt < 2; mt++)
        #pragma unroll
        for (int nt = 0; nt < 4; nt++) {
            int row = r0 + rw + mt * 16 + g;
            int l   = l0 + lw + nt * 8 + 2 * tig;
            size_t i0 = (size_t)row * LVAL + l;
            const float* c = acc[mt * 4 + nt];
            float2 xv = *(const float2*)(x + i0);
            *(float2*)(out + i0) = make_float2(xv.x + c[0], xv.y + c[1]);
            size_t i1 = i0 + (size_t)8 * LVAL;
            float2 xw = *(const float2*)(x + i1);
            *(float2*)(out + i1) = make_float2(xw.x + c[2], xw.y + c[3]);
        }
}

// ---------------- launch ----------------
extern "C" void kernel_launch(void* const* d_in, const int* in_sizes, int n_in,
                              void* d_out, int out_size) {
    const float* x = (const float*)d_in[0];
    float* out = (float*)d_out;
    (void)in_sizes; (void)n_in; (void)out_size;

    static bool attr_done = false;
    if (!attr_done) {
        cudaFuncSetAttribute(k2_proj, cudaFuncAttributeMaxDynamicSharedMemorySize, K2_SMEM_BYTES);
        cudaFuncSetAttribute(k4_attn, cudaFuncAttributeMaxDynamicSharedMemorySize, K4_SMEM_BYTES);
        attr_done = true;
    }

    k1_build<<<(NB * LVAL + 255) / 256, 256>>>();
    k2_proj<<<dim3(NROWS / 64, 4), 256, K2_SMEM_BYTES>>>(x);
    k3_softmax<<<NROWS / 8, 256>>>();
    k4_attn<<<dim3(LVAL / 128, NROWS / 64), 256, K4_SMEM_BYTES>>>(x, out);
}

// round 9
// speedup vs baseline: 1.9466x; 1.2275x over previous
#include <cuda_runtime.h>
#include <cuda_fp16.h>
#include <cstdint>

#define LVAL 4096
#define NB 64
#define NROWS 16384            // 32*512
#define PW 36                  // padded row stride in u32 words (32 data words + 4 pad)
#define RADIUS 0.9

// ---------------- device globals (no allocs allowed) ----------------
__device__ __half g_Bh [NB * LVAL];    // Blaschke hi split, [n][l] l-contig
__device__ __half g_Bl [NB * LVAL];    // lo split
__device__ __half g_BTh[LVAL * NB];    // transposed hi split, [l][n] n-contig
__device__ __half g_BTl[LVAL * NB];
__device__ float  g_proj[4 * NROWS * NB];   // split-K partial projections (4 slabs)
__device__ __half g_W0[NROWS * NB];    // softmax weights hi split, [row][n]
__device__ __half g_W1[NROWS * NB];    // lo split

// ---------------- helpers ----------------
__device__ __forceinline__ unsigned smem_u32p(const void* p) {
    return (unsigned)__cvta_generic_to_shared(p);
}
__device__ __forceinline__ void cp16(unsigned dst, const void* src) {
    asm volatile("cp.async.ca.shared.global [%0], [%1], 16;\n" :: "r"(dst), "l"(src));
}
__device__ __forceinline__ void cp_commit() {
    asm volatile("cp.async.commit_group;\n" ::: "memory");
}
template <int N>
__device__ __forceinline__ void cp_wait() {
    asm volatile("cp.async.wait_group %0;\n" :: "n"(N) : "memory");
}
__device__ __forceinline__ uint32_t packh(__half a, __half b) {
    __half2 h = __halves2half2(a, b);
    return *reinterpret_cast<uint32_t*>(&h);
}
__device__ __forceinline__ uint32_t pack_rn(float a, float b) {
    return packh(__float2half_rn(a), __float2half_rn(b));
}

// D(16x8) += A(16x16) * B(16x8), fp16 inputs, fp32 accum
__device__ __forceinline__ void mma16(float* c, const uint32_t* a, const uint32_t* b) {
    asm volatile(
        "mma.sync.aligned.m16n8k16.row.col.f32.f16.f16.f32 "
        "{%0,%1,%2,%3}, {%4,%5,%6,%7}, {%8,%9}, {%0,%1,%2,%3};\n"
        : "+f"(c[0]), "+f"(c[1]), "+f"(c[2]), "+f"(c[3])
        : "r"(a[0]), "r"(a[1]), "r"(a[2]), "r"(a[3]),
          "r"(b[0]), "r"(b[1]));
}

__device__ __forceinline__ void ldsm_x4(uint32_t* r, uint32_t addr) {
    asm volatile("ldmatrix.sync.aligned.m8n8.x4.shared.b16 {%0,%1,%2,%3}, [%4];"
        : "=r"(r[0]), "=r"(r[1]), "=r"(r[2]), "=r"(r[3]) : "r"(addr));
}

// ---------------- k1: build Blaschke basis + fp16 splits ----------------
__global__ void k1_build() {
    int idx = blockIdx.x * blockDim.x + threadIdx.x;
    if (idx >= NB * LVAL) return;
    int n = idx >> 12;
    int l = idx & 4095;
    const double TWO_PI = 6.283185307179586476925286766559;
    double theta = (double)n * (TWO_PI / 64.0);
    double t     = (double)l * (TWO_PI / 4095.0);   // linspace(0,2pi,4096) incl. endpoint
    float c = cosf((float)(t - theta));             // arg exact in double, cos in fp32
    const float r = (float)RADIUS;
    float v = sqrtf(1.0f - r * r) * (1.0f - r * c) / (1.0f - 2.0f * r * c + r * r);
    __half h = __float2half_rn(v);
    __half lo = __float2half_rn(v - __half2float(h));
    g_Bh [n * LVAL + l] = h;
    g_Bl [n * LVAL + l] = lo;
    g_BTh[l * NB + n]   = h;
    g_BTl[l * NB + n]   = lo;
}

// ---------------- k2: proj slab GEMM  (split-K = 4, ldmatrix frags) ----------------
// CTA: 64 rows x 64 basis, K-slice 1024, chunks of 64.
// smem stage (u32 words): xh[0,2304) xl[2304,4608) bh[4608,6912) bl[6912,9216); 2 stages.
#define K2_STAGE 9216
#define K2_SMEM_BYTES (2 * K2_STAGE * 4)

__global__ __launch_bounds__(256, 3) void k2_proj(const float* __restrict__ x) {
    extern __shared__ uint32_t smu[];
    const int tid = threadIdx.x, warp = tid >> 5, lane = tid & 31;
    const int g = lane >> 2, tig = lane & 3;
    const int r0 = blockIdx.x * 64;
    const int kb0 = blockIdx.y * 1024;
    const int rw = (warp & 3) * 16;      // warp x-row offset (A operand, m)
    const int nw = (warp >> 2) * 32;     // warp basis offset (B operand, n)
    const int quad = tid & 15, rloc = tid >> 4;

    // ldmatrix lane address components
    const int arow   = lane & 15;
    const int acol16 = (lane >> 4) & 1;
    const int brow   = lane & 7;
    const int bcol16 = (lane >> 3) & 1;
    const int bpair  = (lane >> 4) & 1;

    float acc[4][4];
    #pragma unroll
    for (int i = 0; i < 4; i++)
        #pragma unroll
        for (int j = 0; j < 4; j++) acc[i][j] = 0.f;

    auto stage = [&](int c) {
        uint32_t* b = smu + (c & 1) * K2_STAGE;
        const int kbase = kb0 + c * 64;
        #pragma unroll
        for (int j = 0; j < 2; j++) {
            int e = tid + j * 256; int row = e >> 3, seg = e & 7;
            cp16(smem_u32p(b + 4608 + row * PW + seg * 4),
                 g_Bh + (size_t)row * LVAL + kbase + seg * 8);
            cp16(smem_u32p(b + 6912 + row * PW + seg * 4),
                 g_Bl + (size_t)row * LVAL + kbase + seg * 8);
        }
        cp_commit();
        #pragma unroll
        for (int i = 0; i < 4; i++) {
            int row = rloc + i * 16;
            const float4 v = *(const float4*)(x + (size_t)(r0 + row) * LVAL + kbase + quad * 4);
            __half hx = __float2half_rn(v.x), hy = __float2half_rn(v.y);
            __half hz = __float2half_rn(v.z), hw = __float2half_rn(v.w);
            uint32_t h01 = packh(hx, hy), h23 = packh(hz, hw);
            uint32_t l01 = pack_rn(v.x - __half2float(hx), v.y - __half2float(hy));
            uint32_t l23 = pack_rn(v.z - __half2float(hz), v.w - __half2float(hw));
            *(uint2*)(b + row * PW + quad * 2)        = make_uint2(h01, h23);
            *(uint2*)(b + 2304 + row * PW + quad * 2) = make_uint2(l01, l23);
        }
    };

    stage(0);
    for (int c = 0; c < 16; c++) {
        if (c + 1 < 16) { stage(c + 1); cp_wait<1>(); }
        else            { cp_wait<0>(); }
        __syncthreads();

        const uint32_t* buf = smu + (c & 1) * K2_STAGE;
        const uint32_t aHi = smem_u32p(buf +        (rw + arow) * PW) + acol16 * 16;
        const uint32_t aLo = smem_u32p(buf + 2304 + (rw + arow) * PW) + acol16 * 16;
        const uint32_t bHi = smem_u32p(buf + 4608 + (nw + bpair * 8 + brow) * PW) + bcol16 * 16;
        const uint32_t bLo = smem_u32p(buf + 6912 + (nw + bpair * 8 + brow) * PW) + bcol16 * 16;

        #pragma unroll
        for (int ks = 0; ks < 4; ks++) {
            const int kb = ks * 32;   // 16 halfs per k-step
            uint32_t ah[4], al[4], bh[2][4], bl[2][4];
            ldsm_x4(ah, aHi + kb);
            ldsm_x4(al, aLo + kb);
            #pragma unroll
            for (int p = 0; p < 2; p++) {
                ldsm_x4(bh[p], bHi + p * (16 * PW * 4) + kb);
                ldsm_x4(bl[p], bLo + p * (16 * PW * 4) + kb);
            }
            #pragma unroll
            for (int nt = 0; nt < 4; nt++) {
                const int p = nt >> 1, o = (nt & 1) * 2;
                mma16(acc[nt], ah, &bh[p][o]);
                mma16(acc[nt], ah, &bl[p][o]);
                mma16(acc[nt], al, &bh[p][o]);
            }
        }
        __syncthreads();
    }

    float* slab = g_proj + (size_t)blockIdx.y * (NROWS * NB);
    #pragma unroll
    for (int nt = 0; nt < 4; nt++) {
        int col = nw + nt * 8 + 2 * tig;
        int row = r0 + rw + g;
        *(float2*)(slab + (size_t)row * NB + col)       = make_float2(acc[nt][0], acc[nt][1]);
        *(float2*)(slab + (size_t)(row + 8) * NB + col) = make_float2(acc[nt][2], acc[nt][3]);
    }
}

// ---------------- k3: reduce slabs + softmax(|.|) + fp16 W split ----------------
__global__ __launch_bounds__(256) void k3_softmax() {
    const int warp = threadIdx.x >> 5, lane = threadIdx.x & 31;
    const int row = blockIdx.x * 8 + warp;
    const size_t base = (size_t)row * NB + 2 * lane;
    float p0 = 0.f, p1 = 0.f;
    #pragma unroll
    for (int s = 0; s < 4; s++) {
        float2 v = *(const float2*)(g_proj + (size_t)s * (NROWS * NB) + base);
        p0 += v.x; p1 += v.y;
    }
    float a0 = fabsf(p0), a1 = fabsf(p1);
    float m = fmaxf(a0, a1);
    #pragma unroll
    for (int o = 16; o > 0; o >>= 1) m = fmaxf(m, __shfl_xor_sync(0xffffffffu, m, o));
    float e0 = __expf(a0 - m), e1 = __expf(a1 - m);
    float s = e0 + e1;
    #pragma unroll
    for (int o = 16; o > 0; o >>= 1) s += __shfl_xor_sync(0xffffffffu, s, o);
    float inv = 1.0f / s;
    float w0 = e0 * inv, w1 = e1 * inv;
    __half h0 = __float2half_rn(w0), h1 = __float2half_rn(w1);
    *(uint32_t*)&g_W0[base] = packh(h0, h1);
    *(uint32_t*)&g_W1[base] = pack_rn(w0 - __half2float(h0), w1 - __half2float(h1));
}

// ---------------- k4: out = x + W*B  (64 rows x 128 l per CTA) ----------------
// smem (u32 words): Wh[0,2304) Wl[2304,4608) BTh[4608,9216) BTl[9216,13824)
// epilogue reuses smem as fp32 attn staging [64][132]
#define K4_SMEM_WORDS 13824
#define K4_SMEM_BYTES (K4_SMEM_WORDS * 4)
#define SE 132                 // epilogue staging stride (floats)

__global__ __launch_bounds__(256, 3) void k4_attn(
    const float* __restrict__ x, float* __restrict__ out)
{
    extern __shared__ uint32_t smu[];
    const int tid = threadIdx.x, warp = tid >> 5, lane = tid & 31;
    const int g = lane >> 2, tig = lane & 3;
    const int r0 = blockIdx.y * 64;
    const int l0 = blockIdx.x * 128;
    const int rw = (warp & 1) * 32;      // warp row offset (2 groups of 32)
    const int lw = (warp >> 1) * 32;     // warp l offset   (4 groups of 32)

    // -------- stage W (64 rows) and BT (128 rows) hi/lo via cp.async --------
    #pragma unroll
    for (int j = 0; j < 2; j++) {
        int e = tid + j * 256; int row = e >> 3, seg = e & 7;
        cp16(smem_u32p(smu + 0    + row * PW + seg * 4), g_W0 + (size_t)(r0 + row) * NB + seg * 8);
        cp16(smem_u32p(smu + 2304 + row * PW + seg * 4), g_W1 + (size_t)(r0 + row) * NB + seg * 8);
    }
    #pragma unroll
    for (int j = 0; j < 4; j++) {
        int e = tid + j * 256; int row = e >> 3, seg = e & 7;
        cp16(smem_u32p(smu + 4608 + row * PW + seg * 4), g_BTh + (size_t)(l0 + row) * NB + seg * 8);
        cp16(smem_u32p(smu + 9216 + row * PW + seg * 4), g_BTl + (size_t)(l0 + row) * NB + seg * 8);
    }
    cp_commit();
    cp_wait<0>();
    __syncthreads();

    // -------- per-lane ldmatrix base addresses --------
    const int arow   = lane & 15;
    const int acol16 = (lane >> 4) & 1;
    const uint32_t aHi = smem_u32p(smu +        (rw + arow) * PW) + acol16 * 16;
    const uint32_t aLo = smem_u32p(smu + 2304 + (rw + arow) * PW) + acol16 * 16;
    const int brow   = lane & 7;
    const int bcol16 = (lane >> 3) & 1;
    const int bpair  = (lane >> 4) & 1;
    const uint32_t bHi = smem_u32p(smu + 4608 + (lw + bpair * 8 + brow) * PW) + bcol16 * 16;
    const uint32_t bLo = smem_u32p(smu + 9216 + (lw + bpair * 8 + brow) * PW) + bcol16 * 16;

    float acc[8][4];
    #pragma unroll
    for (int i = 0; i < 8; i++)
        #pragma unroll
        for (int j = 0; j < 4; j++) acc[i][j] = 0.f;

    #pragma unroll
    for (int ks = 0; ks < 4; ks++) {
        const int kb = ks * 32;
        uint32_t ah[2][4], al[2][4], bh[2][4], bl[2][4];
        #pragma unroll
        for (int mt = 0; mt < 2; mt++) {
            ldsm_x4(ah[mt], aHi + mt * (16 * PW * 4) + kb);
            ldsm_x4(al[mt], aLo + mt * (16 * PW * 4) + kb);
        }
        #pragma unroll
        for (int p = 0; p < 2; p++) {
            ldsm_x4(bh[p], bHi + p * (16 * PW * 4) + kb);
            ldsm_x4(bl[p], bLo + p * (16 * PW * 4) + kb);
        }
        #pragma unroll
        for (int mt = 0; mt < 2; mt++)
            #pragma unroll
            for (int nt = 0; nt < 4; nt++) {
                const int p = nt >> 1, o = (nt & 1) * 2;
                mma16(acc[mt * 4 + nt], ah[mt], &bh[p][o]);
                mma16(acc[mt * 4 + nt], ah[mt], &bl[p][o]);
                mma16(acc[mt * 4 + nt], al[mt], &bh[p][o]);
            }
    }

    // -------- epilogue: stage attn in smem, then coalesced out = x + attn --------
    __syncthreads();                      // everyone done reading W/BT smem
    float* smf = (float*)smu;
    #pragma unroll
    for (int mt = 0; mt < 2; mt++)
        #pragma unroll
        for (int nt = 0; nt < 4; nt++) {
            int row = rw + mt * 16 + g;
            int col = lw + nt * 8 + 2 * tig;
            const float* c = acc[mt * 4 + nt];
            *(float2*)(smf + row * SE + col)       = make_float2(c[0], c[1]);
            *(float2*)(smf + (row + 8) * SE + col) = make_float2(c[2], c[3]);
        }
    __syncthreads();

    #pragma unroll
    for (int pass = 0; pass < 8; pass++) {
        int row = pass * 8 + warp;
        int col = lane * 4;
        float4 a = *(const float4*)(smf + row * SE + col);
        size_t gi = (size_t)(r0 + row) * LVAL + l0 + col;
        float4 xv = *(const float4*)(x + gi);
        *(float4*)(out + gi) =
            make_float4(xv.x + a.x, xv.y + a.y, xv.z + a.z, xv.w + a.w);
    }
}

// ---------------- launch ----------------
extern "C" void kernel_launch(void* const* d_in, const int* in_sizes, int n_in,
                              void* d_out, int out_size) {
    const float* x = (const float*)d_in[0];
    float* out = (float*)d_out;
    (void)in_sizes; (void)n_in; (void)out_size;

    static bool attr_done = false;
    if (!attr_done) {
        cudaFuncSetAttribute(k2_proj, cudaFuncAttributeMaxDynamicSharedMemorySize, K2_SMEM_BYTES);
        cudaFuncSetAttribute(k4_attn, cudaFuncAttributeMaxDynamicSharedMemorySize, K4_SMEM_BYTES);
        attr_done = true;
    }

    k1_build<<<(NB * LVAL + 255) / 256, 256>>>();
    k2_proj<<<dim3(NROWS / 64, 4), 256, K2_SMEM_BYTES>>>(x);
    k3_softmax<<<NROWS / 8, 256>>>();
    k4_attn<<<dim3(LVAL / 128, NROWS / 64), 256, K4_SMEM_BYTES>>>(x, out);
}

// round 11
// speedup vs baseline: 1.9490x; 1.0012x over previous
#include <cuda_runtime.h>
#include <cuda_fp16.h>
#include <cstdint>

#define LVAL 4096
#define NB 64
#define NROWS 16384            // 32*512
#define PW 36                  // padded row stride in u32 words (32 data words + 4 pad)
#define RADIUS 0.9
#define KSPLIT 8

// ---------------- device globals (no allocs allowed) ----------------
__device__ __half g_Bh [NB * LVAL];    // Blaschke hi split, [n][l] l-contig
__device__ __half g_Bl [NB * LVAL];    // lo split
__device__ __half g_BTh[LVAL * NB];    // transposed hi split, [l][n] n-contig
__device__ __half g_BTl[LVAL * NB];
__device__ float  g_proj[KSPLIT * NROWS * NB];   // split-K partial projections
__device__ __half g_W0[NROWS * NB];    // softmax weights hi split, [row][n]
__device__ __half g_W1[NROWS * NB];    // lo split

// ---------------- helpers ----------------
__device__ __forceinline__ unsigned smem_u32p(const void* p) {
    return (unsigned)__cvta_generic_to_shared(p);
}
__device__ __forceinline__ void cp16(unsigned dst, const void* src) {
    asm volatile("cp.async.ca.shared.global [%0], [%1], 16;\n" :: "r"(dst), "l"(src));
}
__device__ __forceinline__ void cp_commit() {
    asm volatile("cp.async.commit_group;\n" ::: "memory");
}
template <int N>
__device__ __forceinline__ void cp_wait() {
    asm volatile("cp.async.wait_group %0;\n" :: "n"(N) : "memory");
}
__device__ __forceinline__ uint32_t packh(__half a, __half b) {
    __half2 h = __halves2half2(a, b);
    return *reinterpret_cast<uint32_t*>(&h);
}
__device__ __forceinline__ uint32_t pack_rn(float a, float b) {
    return packh(__float2half_rn(a), __float2half_rn(b));
}

// D(16x8) += A(16x16) * B(16x8), fp16 inputs, fp32 accum
__device__ __forceinline__ void mma16(float* c, const uint32_t* a, const uint32_t* b) {
    asm volatile(
        "mma.sync.aligned.m16n8k16.row.col.f32.f16.f16.f32 "
        "{%0,%1,%2,%3}, {%4,%5,%6,%7}, {%8,%9}, {%0,%1,%2,%3};\n"
        : "+f"(c[0]), "+f"(c[1]), "+f"(c[2]), "+f"(c[3])
        : "r"(a[0]), "r"(a[1]), "r"(a[2]), "r"(a[3]),
          "r"(b[0]), "r"(b[1]));
}

__device__ __forceinline__ void ldsm_x4(uint32_t* r, uint32_t addr) {
    asm volatile("ldmatrix.sync.aligned.m8n8.x4.shared.b16 {%0,%1,%2,%3}, [%4];"
        : "=r"(r[0]), "=r"(r[1]), "=r"(r[2]), "=r"(r[3]) : "r"(addr));
}

// ---------------- k1: build Blaschke basis + fp16 splits ----------------
__global__ void k1_build() {
    int idx = blockIdx.x * blockDim.x + threadIdx.x;
    if (idx >= NB * LVAL) return;
    int n = idx >> 12;
    int l = idx & 4095;
    const double TWO_PI = 6.283185307179586476925286766559;
    double theta = (double)n * (TWO_PI / 64.0);
    double t     = (double)l * (TWO_PI / 4095.0);   // linspace(0,2pi,4096) incl. endpoint
    float c = cosf((float)(t - theta));             // arg exact in double, cos in fp32
    const float r = (float)RADIUS;
    float v = sqrtf(1.0f - r * r) * (1.0f - r * c) / (1.0f - 2.0f * r * c + r * r);
    __half h = __float2half_rn(v);
    __half lo = __float2half_rn(v - __half2float(h));
    g_Bh [n * LVAL + l] = h;
    g_Bl [n * LVAL + l] = lo;
    g_BTh[l * NB + n]   = h;
    g_BTl[l * NB + n]   = lo;
}

// ---------------- k2: proj slab GEMM  (split-K = 8, 128-row CTA, ldmatrix frags) ----
// CTA: 128 rows x 64 basis, K-slice 512, 8 chunks of 64, double-buffered.
// stage layout (u32 words): xh[0,4608) xl[4608,9216) bh[9216,11520) bl[11520,13824)
#define K2_STAGE 13824
#define K2_SMEM_BYTES (2 * K2_STAGE * 4)   // 110592

__global__ __launch_bounds__(256, 2) void k2_proj(const float* __restrict__ x) {
    extern __shared__ uint32_t smu[];
    const int tid = threadIdx.x, warp = tid >> 5, lane = tid & 31;
    const int g = lane >> 2, tig = lane & 3;
    const int r0 = blockIdx.x * 128;
    const int kslab = blockIdx.y * (LVAL / KSPLIT);   // 512
    const int rw = (warp & 3) * 32;      // warp x-row offset (A operand, m)
    const int nw = (warp >> 2) * 32;     // warp basis offset (B operand, n)
    const int quad = tid & 15, rloc = tid >> 4;

    // ldmatrix lane address components
    const int arow   = lane & 15;
    const int acol16 = (lane >> 4) & 1;
    const int brow   = lane & 7;
    const int bcol16 = (lane >> 3) & 1;
    const int bpair  = (lane >> 4) & 1;

    float acc[8][4];
    #pragma unroll
    for (int i = 0; i < 8; i++)
        #pragma unroll
        for (int j = 0; j < 4; j++) acc[i][j] = 0.f;

    auto stage = [&](int c) {
        uint32_t* b = smu + (c & 1) * K2_STAGE;
        const int kbase = kslab + c * 64;
        // B hi/lo via cp.async (64 basis rows x 64 k)
        #pragma unroll
        for (int j = 0; j < 2; j++) {
            int e = tid + j * 256; int n = e >> 3, seg = e & 7;
            cp16(smem_u32p(b + 9216  + n * PW + seg * 4),
                 g_Bh + (size_t)n * LVAL + kbase + seg * 8);
            cp16(smem_u32p(b + 11520 + n * PW + seg * 4),
                 g_Bl + (size_t)n * LVAL + kbase + seg * 8);
        }
        cp_commit();
        // x: LDG fp32 -> hi/lo fp16 split -> STS (128 rows x 64 k)
        #pragma unroll
        for (int i = 0; i < 8; i++) {
            int row = rloc + i * 16;
            const float4 v = *(const float4*)(x + (size_t)(r0 + row) * LVAL + kbase + quad * 4);
            __half hx = __float2half_rn(v.x), hy = __float2half_rn(v.y);
            __half hz = __float2half_rn(v.z), hw = __float2half_rn(v.w);
            uint32_t h01 = packh(hx, hy), h23 = packh(hz, hw);
            uint32_t l01 = pack_rn(v.x - __half2float(hx), v.y - __half2float(hy));
            uint32_t l23 = pack_rn(v.z - __half2float(hz), v.w - __half2float(hw));
            *(uint2*)(b + row * PW + quad * 2)        = make_uint2(h01, h23);
            *(uint2*)(b + 4608 + row * PW + quad * 2) = make_uint2(l01, l23);
        }
    };

    stage(0);
    for (int c = 0; c < KSPLIT; c++) {
        if (c + 1 < KSPLIT) { stage(c + 1); cp_wait<1>(); }
        else                { cp_wait<0>(); }
        __syncthreads();

        const uint32_t* buf = smu + (c & 1) * K2_STAGE;
        const uint32_t aHi = smem_u32p(buf +        (rw + arow) * PW) + acol16 * 16;
        const uint32_t aLo = smem_u32p(buf + 4608 + (rw + arow) * PW) + acol16 * 16;
        const uint32_t bHi = smem_u32p(buf + 9216  + (nw + bpair * 8 + brow) * PW) + bcol16 * 16;
        const uint32_t bLo = smem_u32p(buf + 11520 + (nw + bpair * 8 + brow) * PW) + bcol16 * 16;

        #pragma unroll
        for (int ks = 0; ks < 4; ks++) {
            const int kb = ks * 32;   // 16 halfs per k-step
            uint32_t ah[2][4], al[2][4], bh[2][4], bl[2][4];
            #pragma unroll
            for (int mt = 0; mt < 2; mt++) {
                ldsm_x4(ah[mt], aHi + mt * (16 * PW * 4) + kb);
                ldsm_x4(al[mt], aLo + mt * (16 * PW * 4) + kb);
            }
            #pragma unroll
            for (int p = 0; p < 2; p++) {
                ldsm_x4(bh[p], bHi + p * (16 * PW * 4) + kb);
                ldsm_x4(bl[p], bLo + p * (16 * PW * 4) + kb);
            }
            #pragma unroll
            for (int mt = 0; mt < 2; mt++)
                #pragma unroll
                for (int nt = 0; nt < 4; nt++) {
                    const int p = nt >> 1, o = (nt & 1) * 2;
                    mma16(acc[mt * 4 + nt], ah[mt], &bh[p][o]);
                    mma16(acc[mt * 4 + nt], ah[mt], &bl[p][o]);
                    mma16(acc[mt * 4 + nt], al[mt], &bh[p][o]);
                }
        }
        __syncthreads();
    }

    float* slab = g_proj + (size_t)blockIdx.y * (NROWS * NB);
    #pragma unroll
    for (int mt = 0; mt < 2; mt++)
        #pragma unroll
        for (int nt = 0; nt < 4; nt++) {
            int col = nw + nt * 8 + 2 * tig;
            int row = r0 + rw + mt * 16 + g;
            const float* cacc = acc[mt * 4 + nt];
            *(float2*)(slab + (size_t)row * NB + col)       = make_float2(cacc[0], cacc[1]);
            *(float2*)(slab + (size_t)(row + 8) * NB + col) = make_float2(cacc[2], cacc[3]);
        }
}

// ---------------- k3: reduce slabs + softmax(|.|) + fp16 W split ----------------
__global__ __launch_bounds__(256) void k3_softmax() {
    const int warp = threadIdx.x >> 5, lane = threadIdx.x & 31;
    const int row = blockIdx.x * 8 + warp;
    const size_t base = (size_t)row * NB + 2 * lane;
    float p0 = 0.f, p1 = 0.f;
    #pragma unroll
    for (int s = 0; s < KSPLIT; s++) {
        float2 v = *(const float2*)(g_proj + (size_t)s * (NROWS * NB) + base);
        p0 += v.x; p1 += v.y;
    }
    float a0 = fabsf(p0), a1 = fabsf(p1);
    float m = fmaxf(a0, a1);
    #pragma unroll
    for (int o = 16; o > 0; o >>= 1) m = fmaxf(m, __shfl_xor_sync(0xffffffffu, m, o));
    float e0 = __expf(a0 - m), e1 = __expf(a1 - m);
    float s = e0 + e1;
    #pragma unroll
    for (int o = 16; o > 0; o >>= 1) s += __shfl_xor_sync(0xffffffffu, s, o);
    float inv = 1.0f / s;
    float w0 = e0 * inv, w1 = e1 * inv;
    __half h0 = __float2half_rn(w0), h1 = __float2half_rn(w1);
    *(uint32_t*)&g_W0[base] = packh(h0, h1);
    *(uint32_t*)&g_W1[base] = pack_rn(w0 - __half2float(h0), w1 - __half2float(h1));
}

// ---------------- k4: out = x + W*B  (64 rows x 128 l per CTA) ----------------
// smem (u32 words): Wh[0,2304) Wl[2304,4608) BTh[4608,9216) BTl[9216,13824)
// epilogue reuses smem as fp32 attn staging [64][132]
#define K4_SMEM_WORDS 13824
#define K4_SMEM_BYTES (K4_SMEM_WORDS * 4)
#define SE 132                 // epilogue staging stride (floats)

__global__ __launch_bounds__(256, 3) void k4_attn(
    const float* __restrict__ x, float* __restrict__ out)
{
    extern __shared__ uint32_t smu[];
    const int tid = threadIdx.x, warp = tid >> 5, lane = tid & 31;
    const int g = lane >> 2, tig = lane & 3;
    const int r0 = blockIdx.y * 64;
    const int l0 = blockIdx.x * 128;
    const int rw = (warp & 1) * 32;      // warp row offset (2 groups of 32)
    const int lw = (warp >> 1) * 32;     // warp l offset   (4 groups of 32)

    // -------- stage W (64 rows) and BT (128 rows) hi/lo via cp.async --------
    #pragma unroll
    for (int j = 0; j < 2; j++) {
        int e = tid + j * 256; int row = e >> 3, seg = e & 7;
        cp16(smem_u32p(smu + 0    + row * PW + seg * 4), g_W0 + (size_t)(r0 + row) * NB + seg * 8);
        cp16(smem_u32p(smu + 2304 + row * PW + seg * 4), g_W1 + (size_t)(r0 + row) * NB + seg * 8);
    }
    #pragma unroll
    for (int j = 0; j < 4; j++) {
        int e = tid + j * 256; int row = e >> 3, seg = e & 7;
        cp16(smem_u32p(smu + 4608 + row * PW + seg * 4), g_BTh + (size_t)(l0 + row) * NB + seg * 8);
        cp16(smem_u32p(smu + 9216 + row * PW + seg * 4), g_BTl + (size_t)(l0 + row) * NB + seg * 8);
    }
    cp_commit();
    cp_wait<0>();
    __syncthreads();

    // -------- per-lane ldmatrix base addresses --------
    const int arow   = lane & 15;
    const int acol16 = (lane >> 4) & 1;
    const uint32_t aHi = smem_u32p(smu +        (rw + arow) * PW) + acol16 * 16;
    const uint32_t aLo = smem_u32p(smu + 2304 + (rw + arow) * PW) + acol16 * 16;
    const int brow   = lane & 7;
    const int bcol16 = (lane >> 3) & 1;
    const int bpair  = (lane >> 4) & 1;
    const uint32_t bHi = smem_u32p(smu + 4608 + (lw + bpair * 8 + brow) * PW) + bcol16 * 16;
    const uint32_t bLo = smem_u32p(smu + 9216 + (lw + bpair * 8 + brow) * PW) + bcol16 * 16;

    float acc[8][4];
    #pragma unroll
    for (int i = 0; i < 8; i++)
        #pragma unroll
        for (int j = 0; j < 4; j++) acc[i][j] = 0.f;

    #pragma unroll
    for (int ks = 0; ks < 4; ks++) {
        const int kb = ks * 32;
        uint32_t ah[2][4], al[2][4], bh[2][4], bl[2][4];
        #pragma unroll
        for (int mt = 0; mt < 2; mt++) {
            ldsm_x4(ah[mt], aHi + mt * (16 * PW * 4) + kb);
            ldsm_x4(al[mt], aLo + mt * (16 * PW * 4) + kb);
        }
        #pragma unroll
        for (int p = 0; p < 2; p++) {
            ldsm_x4(bh[p], bHi + p * (16 * PW * 4) + kb);
            ldsm_x4(bl[p], bLo + p * (16 * PW * 4) + kb);
        }
        #pragma unroll
        for (int mt = 0; mt < 2; mt++)
            #pragma unroll
            for (int nt = 0; nt < 4; nt++) {
                const int p = nt >> 1, o = (nt & 1) * 2;
                mma16(acc[mt * 4 + nt], ah[mt], &bh[p][o]);
                mma16(acc[mt * 4 + nt], ah[mt], &bl[p][o]);
                mma16(acc[mt * 4 + nt], al[mt], &bh[p][o]);
            }
    }

    // -------- epilogue: stage attn in smem, then coalesced out = x + attn --------
    __syncthreads();                      // everyone done reading W/BT smem
    float* smf = (float*)smu;
    #pragma unroll
    for (int mt = 0; mt < 2; mt++)
        #pragma unroll
        for (int nt = 0; nt < 4; nt++) {
            int row = rw + mt * 16 + g;
            int col = lw + nt * 8 + 2 * tig;
            const float* c = acc[mt * 4 + nt];
            *(float2*)(smf + row * SE + col)       = make_float2(c[0], c[1]);
            *(float2*)(smf + (row + 8) * SE + col) = make_float2(c[2], c[3]);
        }
    __syncthreads();

    #pragma unroll
    for (int pass = 0; pass < 8; pass++) {
        int row = pass * 8 + warp;
        int col = lane * 4;
        float4 a = *(const float4*)(smf + row * SE + col);
        size_t gi = (size_t)(r0 + row) * LVAL + l0 + col;
        float4 xv = *(const float4*)(x + gi);
        *(float4*)(out + gi) =
            make_float4(xv.x + a.x, xv.y + a.y, xv.z + a.z, xv.w + a.w);
    }
}

// ---------------- launch ----------------
extern "C" void kernel_launch(void* const* d_in, const int* in_sizes, int n_in,
                              void* d_out, int out_size) {
    const float* x = (const float*)d_in[0];
    float* out = (float*)d_out;
    (void)in_sizes; (void)n_in; (void)out_size;

    static bool attr_done = false;
    if (!attr_done) {
        cudaFuncSetAttribute(k2_proj, cudaFuncAttributeMaxDynamicSharedMemorySize, K2_SMEM_BYTES);
        cudaFuncSetAttribute(k4_attn, cudaFuncAttributeMaxDynamicSharedMemorySize, K4_SMEM_BYTES);
        attr_done = true;
    }

    k1_build<<<(NB * LVAL + 255) / 256, 256>>>();
    k2_proj<<<dim3(NROWS / 128, KSPLIT), 256, K2_SMEM_BYTES>>>(x);
    k3_softmax<<<NROWS / 8, 256>>>();
    k4_attn<<<dim3(LVAL / 128, NROWS / 64), 256, K4_SMEM_BYTES>>>(x, out);
}